// round 12
// baseline (speedup 1.0000x reference)
#include <cuda_runtime.h>

#define BB 8
#define NN 8192
#define NP 2048
#define KK 16
#define FF 64
#define PP (BB*NP*KK)
#define PTSN (BB*NN)
#define IINF 0x7fffffff

typedef unsigned long long ull;
typedef unsigned int uint;

__device__ float g_Z1[(size_t)PTSN*FF];
__device__ float g_buf[(size_t)PP*FF];
__device__ int   g_fps[BB*NP];
__device__ int   g_knn[PP];
__device__ float g_stats[256];
__device__ float g_sc[256];
__device__ __align__(16) float g_sxs[PTSN];
__device__ __align__(16) float g_sys[PTSN];
__device__ __align__(16) float g_szs[PTSN];
__device__ __align__(16) int   g_sid[PTSN];
__device__ int   g_tmp[PTSN];

__global__ void k_zero() { g_stats[threadIdx.x] = 0.f; }

// ---- packed f32x2 helpers (per-lane IEEE rn, identical to scalar) ----
__device__ __forceinline__ ull pk2(float lo, float hi) {
    ull r; asm("mov.b64 %0, {%1,%2};" : "=l"(r) : "f"(lo), "f"(hi)); return r;
}
__device__ __forceinline__ void upk2(ull v, float& lo, float& hi) {
    asm("mov.b64 {%0,%1}, %2;" : "=f"(lo), "=f"(hi) : "l"(v));
}
__device__ __forceinline__ ull add2(ull a, ull b) {
    ull r; asm("add.rn.f32x2 %0, %1, %2;" : "=l"(r) : "l"(a), "l"(b)); return r;
}
__device__ __forceinline__ ull mul2(ull a, ull b) {
    ull r; asm("mul.rn.f32x2 %0, %1, %2;" : "=l"(r) : "l"(a), "l"(b)); return r;
}

// ---------------- binning: Morton cells + per-chunk sort by original index ----------------
__device__ __forceinline__ int cell_of(float x, float y, float z) {
    int cx = (int)floorf(x + 4.0f); cx = cx < 0 ? 0 : (cx > 7 ? 7 : cx);
    int cy = (int)floorf(y + 4.0f); cy = cy < 0 ? 0 : (cy > 7 ? 7 : cy);
    int cz = (int)floorf(z + 4.0f); cz = cz < 0 ? 0 : (cz > 7 ? 7 : cz);
    int m = 0;
    #pragma unroll
    for (int bit = 0; bit < 3; bit++) {
        m |= ((cx >> bit) & 1) << (3*bit);
        m |= ((cy >> bit) & 1) << (3*bit + 1);
        m |= ((cz >> bit) & 1) << (3*bit + 2);
    }
    return m;
}

__global__ __launch_bounds__(256) void k_bin(const float* __restrict__ xyz) {
    __shared__ int hist[512];
    int b = blockIdx.x, tid = threadIdx.x, lane = tid & 31, w = tid >> 5;
    const float* X = xyz + (size_t)b*3*NN;
    for (int i = tid; i < 512; i += 256) hist[i] = 0;
    __syncthreads();
    for (int i = tid; i < NN; i += 256)
        atomicAdd(&hist[cell_of(X[i], X[NN+i], X[2*NN+i])], 1);
    __syncthreads();
    if (tid == 0) {
        int run = 0;
        for (int c = 0; c < 512; c++) { int t = hist[c]; hist[c] = run; run += t; }
    }
    __syncthreads();
    for (int i = tid; i < NN; i += 256) {
        int c = cell_of(X[i], X[NN+i], X[2*NN+i]);
        int pos = atomicAdd(&hist[c], 1);
        g_tmp[b*NN + pos] = i;
    }
    __syncthreads();
    // warp per 32-chunk: bitonic-sort chunk's original indices ascending, gather coords
    for (int c = w; c < NN/32; c += 8) {
        int key = g_tmp[b*NN + c*32 + lane];
        #pragma unroll
        for (int k = 2; k <= 32; k <<= 1) {
            #pragma unroll
            for (int j = k >> 1; j > 0; j >>= 1) {
                int other = __shfl_xor_sync(0xffffffffu, key, j);
                bool takeMin = (((lane & j) == 0) == ((lane & k) == 0));
                int mn = min(key, other), mx = max(key, other);
                key = takeMin ? mn : mx;
            }
        }
        int sp = b*NN + c*32 + lane;
        g_sid[sp] = key;
        g_sxs[sp] = X[key]; g_sys[sp] = X[NN+key]; g_szs[sp] = X[2*NN+key];
    }
}

// ---------------- FPS: one block/batch, 256 thr x 32 sorted pts, warp-AABB pruning ----------------
__global__ __launch_bounds__(256) void k_fps(const float* __restrict__ xyz,
                                             float* __restrict__ onx) {
    extern __shared__ float sm[];
    float* sx = sm; float* sy = sm + NN; float* sz = sm + 2*NN;
    int*  ssid = (int*)(sm + 3*NN);            // NN
    uint* rvu = (uint*)(ssid + NN);            // 16 (2x8 double-buffered)
    int*  ri  = (int*)(rvu + 16);              // 16
    int*  rp  = (int*)(ri + 16);               // 16

    int b = blockIdx.x, tid = threadIdx.x, lane = tid & 31, wid = tid >> 5;
    int base = tid*32;
    const float* X  = xyz + (size_t)b*3*NN;
    const float* SX = g_sxs + (size_t)b*NN;
    const float* SY = g_sys + (size_t)b*NN;
    const float* SZ = g_szs + (size_t)b*NN;
    float* OX = onx + (size_t)b*3*NP;

    ull xp[16], yp[16], zp[16];
    float dmin[32];
    float lox = 3e38f, hix = -3e38f, loy = 3e38f, hiy = -3e38f, loz = 3e38f, hiz = -3e38f;
    #pragma unroll
    for (int i = 0; i < 32; i += 4) {
        float4 vx = *(const float4*)(SX + base + i);
        float4 vy = *(const float4*)(SY + base + i);
        float4 vz = *(const float4*)(SZ + base + i);
        xp[i/2]   = pk2(vx.x, vx.y); xp[i/2+1] = pk2(vx.z, vx.w);
        yp[i/2]   = pk2(vy.x, vy.y); yp[i/2+1] = pk2(vy.z, vy.w);
        zp[i/2]   = pk2(vz.x, vz.y); zp[i/2+1] = pk2(vz.z, vz.w);
        sx[base+i]=vx.x; sx[base+i+1]=vx.y; sx[base+i+2]=vx.z; sx[base+i+3]=vx.w;
        sy[base+i]=vy.x; sy[base+i+1]=vy.y; sy[base+i+2]=vy.z; sy[base+i+3]=vy.w;
        sz[base+i]=vz.x; sz[base+i+1]=vz.y; sz[base+i+2]=vz.z; sz[base+i+3]=vz.w;
        lox = fminf(lox, fminf(fminf(vx.x,vx.y), fminf(vx.z,vx.w)));
        hix = fmaxf(hix, fmaxf(fmaxf(vx.x,vx.y), fmaxf(vx.z,vx.w)));
        loy = fminf(loy, fminf(fminf(vy.x,vy.y), fminf(vy.z,vy.w)));
        hiy = fmaxf(hiy, fmaxf(fmaxf(vy.x,vy.y), fmaxf(vy.z,vy.w)));
        loz = fminf(loz, fminf(fminf(vz.x,vz.y), fminf(vz.z,vz.w)));
        hiz = fmaxf(hiz, fmaxf(fmaxf(vz.x,vz.y), fmaxf(vz.z,vz.w)));
    }
    // warp AABB (uniform across lanes)
    #pragma unroll
    for (int off = 16; off; off >>= 1) {
        lox = fminf(lox, __shfl_xor_sync(0xffffffffu, lox, off));
        hix = fmaxf(hix, __shfl_xor_sync(0xffffffffu, hix, off));
        loy = fminf(loy, __shfl_xor_sync(0xffffffffu, loy, off));
        hiy = fmaxf(hiy, __shfl_xor_sync(0xffffffffu, hiy, off));
        loz = fminf(loz, __shfl_xor_sync(0xffffffffu, loz, off));
        hiz = fmaxf(hiz, __shfl_xor_sync(0xffffffffu, hiz, off));
    }
    #pragma unroll
    for (int i = 0; i < 32; i++) dmin[i] = 1e10f;
    for (int i = tid; i < NN; i += 256) ssid[i] = g_sid[b*NN + i];

    float px = X[0], py = X[NN], pz = X[2*NN];
    if (tid == 0) {
        g_fps[b*NP] = 0;
        OX[0] = px; OX[NP] = py; OX[2*NP] = pz;
    }
    __syncthreads();

    uint cum = 0u; int corig = IINF, cpos = IINF;
    float wB = 3e38f;

    for (int t = 1; t < NP; t++) {
        float bx = fmaxf(fmaxf(__fsub_rd(lox, px), __fsub_rd(px, hix)), 0.f);
        float by = fmaxf(fmaxf(__fsub_rd(loy, py), __fsub_rd(py, hiy)), 0.f);
        float bz = fmaxf(fmaxf(__fsub_rd(loz, pz), __fsub_rd(pz, hiz)), 0.f);
        float bnd = __fadd_rd(__fadd_rd(__fmul_rd(bx,bx), __fmul_rd(by,by)), __fmul_rd(bz,bz));
        if (bnd < __fmul_ru(wB, 1.00001f)) {
            ull npx = pk2(-px, -px), npy = pk2(-py, -py), npz = pk2(-pz, -pz);
            float bestv = 0.f; int besti = IINF;
            #pragma unroll
            for (int j = 0; j < 16; j++) {
                ull dx = add2(xp[j], npx);
                ull dy = add2(yp[j], npy);
                ull dz = add2(zp[j], npz);
                ull d2 = add2(add2(mul2(dx,dx), mul2(dy,dy)), mul2(dz,dz));
                float d0, d1; upk2(d2, d0, d1);
                int i0 = 2*j, i1 = 2*j + 1;
                dmin[i0] = fminf(dmin[i0], d0);
                if (dmin[i0] > bestv) { bestv = dmin[i0]; besti = base + i0; }
                dmin[i1] = fminf(dmin[i1], d1);
                if (dmin[i1] > bestv) { bestv = dmin[i1]; besti = base + i1; }
            }
            uint u  = __float_as_uint(bestv);
            uint um = __reduce_max_sync(0xffffffffu, u);
            int myorig = IINF;
            if (u == um) myorig = ssid[besti];
            int orig = (int)__reduce_min_sync(0xffffffffu, (uint)myorig);
            int posw = (int)__reduce_min_sync(0xffffffffu, (myorig == orig) ? (uint)besti : (uint)IINF);
            cum = um; corig = orig; cpos = posw;
            wB = __uint_as_float(um);
        }
        int bufo = (t & 1)*8;
        if (lane == 0) { rvu[bufo + wid] = cum; ri[bufo + wid] = corig; rp[bufo + wid] = cpos; }
        __syncthreads();
        uint u2 = (lane < 8) ? rvu[bufo + lane] : 0u;
        int  j2 = (lane < 8) ? ri[bufo + lane]  : IINF;
        int  p2 = (lane < 8) ? rp[bufo + lane]  : IINF;
        uint um2 = __reduce_max_sync(0xffffffffu, u2);
        int worig = (int)__reduce_min_sync(0xffffffffu, (u2 == um2) ? (uint)j2 : (uint)IINF);
        int wpos  = (int)__reduce_min_sync(0xffffffffu, (u2 == um2 && j2 == worig) ? (uint)p2 : (uint)IINF);
        px = sx[wpos]; py = sy[wpos]; pz = sz[wpos];
        if (tid == 0) {
            g_fps[b*NP + t] = worig;
            OX[t] = px; OX[NP + t] = py; OX[2*NP + t] = pz;
        }
    }
}

// ---------------- KNN: warp top-32, float-threshold ballot, REDUX maintenance ----------------
__device__ __forceinline__ uint ordu(float d) {
    uint u = __float_as_uint(d);
    return u ^ (((uint)((int)u >> 31)) | 0x80000000u);
}
__device__ __forceinline__ float iordu(uint u) {
    uint v = (u & 0x80000000u) ? (u ^ 0x80000000u) : ~u;
    return __uint_as_float(v);
}

__global__ __launch_bounds__(256) void k_knn(const float* __restrict__ xyz) {
    __shared__ float4 s4[2048];
    int b = blockIdx.y, tid = threadIdx.x, lane = tid & 31, w = tid >> 5;
    const float* X = xyz + (size_t)b*3*NN;
    int q = blockIdx.x*8 + w;
    int qi = g_fps[b*NP + q];
    float qx = X[qi], qy = X[NN+qi], qz = X[2*NN+qi];
    float qq = __fadd_rn(__fadd_rn(__fmul_rn(qx,qx), __fmul_rn(qy,qy)), __fmul_rn(qz,qz));

    for (int j = tid; j < 2048; j += 256) {
        float xx = X[j], yy = X[NN+j], zz = X[2*NN+j];
        float r = __fadd_rn(__fadd_rn(__fmul_rn(xx,xx), __fmul_rn(yy,yy)), __fmul_rn(zz,zz));
        s4[j] = make_float4(xx, yy, zz, r);
    }
    __syncthreads();

    uint hu; int hj;
    uint um; int jm;
    int wlane; float wd;
    {
        float4 c = s4[lane];
        float dot = __fadd_rn(__fadd_rn(__fmul_rn(qx,c.x), __fmul_rn(qy,c.y)), __fmul_rn(qz,c.z));
        float d = __fsub_rn(__fadd_rn(qq, c.w), __fmul_rn(2.0f, dot));
        hu = ordu(d); hj = lane;
        um = __reduce_max_sync(0xffffffffu, hu);
        jm = (int)__reduce_max_sync(0xffffffffu, (hu == um) ? (uint)hj : 0u);
        uint bal = __ballot_sync(0xffffffffu, hu == um && hj == jm);
        wlane = __ffs(bal) - 1;
        wd = iordu(um);
    }
    for (int tile = 0; tile < NN; tile += 2048) {
        if (tile) {
            __syncthreads();
            for (int j = tid; j < 2048; j += 256) {
                int g = tile + j;
                float xx = X[g], yy = X[NN+g], zz = X[2*NN+g];
                float r = __fadd_rn(__fadd_rn(__fmul_rn(xx,xx), __fmul_rn(yy,yy)), __fmul_rn(zz,zz));
                s4[j] = make_float4(xx, yy, zz, r);
            }
            __syncthreads();
        }
        for (int k = (tile == 0 ? 32 : 0); k < 2048; k += 32) {
            float4 c = s4[k + lane];
            float dot = __fadd_rn(__fadd_rn(__fmul_rn(qx,c.x), __fmul_rn(qy,c.y)), __fmul_rn(qz,c.z));
            float d = __fsub_rn(__fadd_rn(qq, c.w), __fmul_rn(2.0f, dot));
            uint m = __ballot_sync(0xffffffffu, d <= wd);
            while (m) {
                int src = __ffs(m) - 1; m &= m - 1;
                float cd = __shfl_sync(0xffffffffu, d, src);
                int cj = tile + k + src;
                uint cu = ordu(cd);
                if (cu < um || (cu == um && cj < jm)) {
                    if (lane == wlane) { hu = cu; hj = cj; }
                    um = __reduce_max_sync(0xffffffffu, hu);
                    jm = (int)__reduce_max_sync(0xffffffffu, (hu == um) ? (uint)hj : 0u);
                    uint bal = __ballot_sync(0xffffffffu, hu == um && hj == jm);
                    wlane = __ffs(bal) - 1;
                    wd = iordu(um);
                }
            }
        }
    }
    int outidx = 0;
    #pragma unroll
    for (int r = 0; r < KK; r++) {
        uint mu = __reduce_min_sync(0xffffffffu, hu);
        uint mj = __reduce_min_sync(0xffffffffu, (hu == mu) ? (uint)hj : (uint)IINF);
        if (lane == r) outidx = (int)mj;
        if (hu == mu && hj == (int)mj) { hu = 0xffffffffu; hj = IINF; }
    }
    if (lane < KK) g_knn[((size_t)b*NP + q)*KK + lane] = outidx;
}

// ---------------- Z1 = W1[:,3:] @ points, per point ----------------
__global__ __launch_bounds__(128) void k_z1(const float* __restrict__ pts,
                                            const float* __restrict__ W1) {
    __shared__ float w[FF*FF];
    int tid = threadIdx.x;
    for (int i = tid; i < FF*FF; i += 128) w[i] = W1[(i>>6)*67 + 3 + (i&63)];
    __syncthreads();
    int p = blockIdx.x*128 + tid;
    int b = p >> 13, n = p & (NN-1);
    float xv[FF];
    #pragma unroll
    for (int f = 0; f < FF; f++) xv[f] = pts[((size_t)b*FF + f)*NN + n];
    float* zr = g_Z1 + (size_t)p*FF;
    for (int o = 0; o < FF; o += 4) {
        float a0=0.f, a1=0.f, a2=0.f, a3=0.f;
        #pragma unroll
        for (int f = 0; f < FF; f++) {
            float xf = xv[f];
            a0 = fmaf(w[(o+0)*FF+f], xf, a0);
            a1 = fmaf(w[(o+1)*FF+f], xf, a1);
            a2 = fmaf(w[(o+2)*FF+f], xf, a2);
            a3 = fmaf(w[(o+3)*FF+f], xf, a3);
        }
        *(float4*)(zr + o) = make_float4(a0, a1, a2, a3);
    }
}

// ---------------- pass1: y1 -> g_buf channel-major ----------------
__global__ __launch_bounds__(128) void k_p1(const float* __restrict__ xyz,
                                            const float* __restrict__ W1,
                                            const float* __restrict__ b1,
                                            const float* __restrict__ nxyz) {
    __shared__ float w0[64], w1s[64], w2s[64], bb[64];
    int tid = threadIdx.x;
    if (tid < 64) {
        w0[tid]  = W1[tid*67 + 0]; w1s[tid] = W1[tid*67 + 1];
        w2s[tid] = W1[tid*67 + 2]; bb[tid]  = b1[tid];
    }
    __syncthreads();
    int pos = blockIdx.x*128 + tid;
    int b = pos >> 15, q = (pos >> 4) & 2047, n = g_knn[pos];
    float cx = nxyz[((size_t)b*3+0)*NP+q], cy = nxyz[((size_t)b*3+1)*NP+q], cz = nxyz[((size_t)b*3+2)*NP+q];
    const float* X = xyz + (size_t)b*3*NN;
    float dx = X[n]-cx, dy = X[NN+n]-cy, dz = X[2*NN+n]-cz;
    const float4* zr = (const float4*)(g_Z1 + (size_t)(b*NN + n)*FF);
    #pragma unroll
    for (int i = 0; i < 16; i++) {
        float4 v = zr[i]; int o = 4*i;
        g_buf[(size_t)(o+0)*PP+pos] = fmaf(w2s[o+0],dz, fmaf(w1s[o+0],dy, fmaf(w0[o+0],dx, v.x+bb[o+0])));
        g_buf[(size_t)(o+1)*PP+pos] = fmaf(w2s[o+1],dz, fmaf(w1s[o+1],dy, fmaf(w0[o+1],dx, v.y+bb[o+1])));
        g_buf[(size_t)(o+2)*PP+pos] = fmaf(w2s[o+2],dz, fmaf(w1s[o+2],dy, fmaf(w0[o+2],dx, v.z+bb[o+2])));
        g_buf[(size_t)(o+3)*PP+pos] = fmaf(w2s[o+3],dz, fmaf(w1s[o+3],dy, fmaf(w0[o+3],dx, v.w+bb[o+3])));
    }
}

// ---------------- per-channel sum/sumsq ----------------
__global__ __launch_bounds__(256) void k_st(int which) {
    int o = blockIdx.y;
    const float* src = g_buf + (size_t)o*PP + blockIdx.x*(PP/16);
    float s = 0.f, s2 = 0.f;
    for (int i = threadIdx.x; i < PP/16; i += 256) {
        float v = src[i]; s += v; s2 = fmaf(v, v, s2);
    }
    #pragma unroll
    for (int off = 16; off; off >>= 1) {
        s  += __shfl_down_sync(0xffffffffu, s,  off);
        s2 += __shfl_down_sync(0xffffffffu, s2, off);
    }
    __shared__ float as[8], as2[8];
    int wid = threadIdx.x >> 5;
    if ((threadIdx.x & 31) == 0) { as[wid] = s; as2[wid] = s2; }
    __syncthreads();
    if (threadIdx.x == 0) {
        float ts = 0.f, ts2 = 0.f;
        #pragma unroll
        for (int w = 0; w < 8; w++) { ts += as[w]; ts2 += as2[w]; }
        atomicAdd(g_stats + which*128 + o, ts);
        atomicAdd(g_stats + which*128 + 64 + o, ts2);
    }
}

__global__ void k_fin(const float* __restrict__ gam, const float* __restrict__ bet, int which) {
    int o = threadIdx.x;
    float m = g_stats[which*128 + o] / (float)PP;
    float v = g_stats[which*128 + 64 + o] / (float)PP - m*m;
    v = fmaxf(v, 0.f);
    float sc = gam[o] * rsqrtf(v + 1e-5f);
    g_sc[which*128 + o] = sc;
    g_sc[which*128 + 64 + o] = bet[o] - m*sc;
}

// ---------------- pass2: bn1+relu -> conv2 (in place) ----------------
__global__ __launch_bounds__(128) void k_p2(const float* __restrict__ W2, const float* __restrict__ b2) {
    __shared__ float w[64*64];
    __shared__ float sc[64], sh[64], bb[64];
    int tid = threadIdx.x;
    for (int i = tid; i < 64*64; i += 128) w[i] = W2[i];
    if (tid < 64) { sc[tid] = g_sc[tid]; sh[tid] = g_sc[64+tid]; bb[tid] = b2[tid]; }
    __syncthreads();
    int pos = blockIdx.x*128 + tid;
    float h[64];
    #pragma unroll
    for (int o = 0; o < 64; o++) {
        float y = g_buf[(size_t)o*PP + pos];
        h[o] = fmaxf(fmaf(y, sc[o], sh[o]), 0.f);
    }
    for (int o = 0; o < 64; o++) {
        float a = bb[o];
        const float* wr = w + o*64;
        #pragma unroll
        for (int f = 0; f < 64; f++) a = fmaf(wr[f], h[f], a);
        g_buf[(size_t)o*PP + pos] = a;
    }
}

// ---------------- pass3: bn2+relu -> conv3 -> max over K ----------------
__global__ __launch_bounds__(128) void k_p3(const float* __restrict__ W3, const float* __restrict__ b3,
                                            float* __restrict__ outf) {
    __shared__ float w[128*64];
    __shared__ float sc[64], sh[64], bb[128];
    int tid = threadIdx.x;
    for (int i = tid; i < 128*64; i += 128) w[i] = W3[i];
    if (tid < 64) { sc[tid] = g_sc[128+tid]; sh[tid] = g_sc[192+tid]; }
    if (tid < 128) bb[tid] = b3[tid];
    __syncthreads();
    int pos = blockIdx.x*128 + tid;
    float h[64];
    #pragma unroll
    for (int o = 0; o < 64; o++) {
        float y = g_buf[(size_t)o*PP + pos];
        h[o] = fmaxf(fmaf(y, sc[o], sh[o]), 0.f);
    }
    int lane = tid & 15;
    int q = pos >> 4;
    int b = q >> 11, qq = q & 2047;
    for (int c = 0; c < 4; c++) {
        float acc[32];
        #pragma unroll
        for (int o = 0; o < 32; o++) {
            const float* wr = w + (c*32 + o)*64;
            float a = bb[c*32 + o];
            #pragma unroll
            for (int f = 0; f < 64; f++) a = fmaf(wr[f], h[f], a);
            acc[o] = a;
        }
        #pragma unroll
        for (int o = 0; o < 32; o++) {
            float v = acc[o];
            #pragma unroll
            for (int off = 1; off < 16; off <<= 1)
                v = fmaxf(v, __shfl_xor_sync(0xffffffffu, v, off));
            acc[o] = v;
        }
        #pragma unroll
        for (int o = 0; o < 32; o++)
            if ((o & 15) == lane)
                outf[((size_t)b*128 + c*32 + o)*NP + qq] = acc[o];
    }
}

extern "C" void kernel_launch(void* const* d_in, const int* in_sizes, int n_in,
                              void* d_out, int out_size) {
    const float* xyz = (const float*)d_in[0];
    const float* pts = (const float*)d_in[1];
    const float* W1  = (const float*)d_in[2];
    const float* b1  = (const float*)d_in[3];
    const float* g1  = (const float*)d_in[4];
    const float* be1 = (const float*)d_in[5];
    const float* W2  = (const float*)d_in[6];
    const float* b2  = (const float*)d_in[7];
    const float* g2  = (const float*)d_in[8];
    const float* be2 = (const float*)d_in[9];
    const float* W3  = (const float*)d_in[10];
    const float* b3  = (const float*)d_in[11];
    float* out  = (float*)d_out;
    float* onx  = out;
    float* ofe  = out + (size_t)BB*3*NP;

    const int FPS_SM = (4*NN + 48)*4;   // coords(3N) + sid(N) + reduce slots
    cudaFuncSetAttribute(k_fps, cudaFuncAttributeMaxDynamicSharedMemorySize, FPS_SM);

    k_zero<<<1, 256>>>();
    k_bin<<<BB, 256>>>(xyz);
    k_fps<<<BB, 256, FPS_SM>>>(xyz, onx);
    k_knn<<<dim3(NP/8, BB), 256>>>(xyz);
    k_z1<<<PTSN/128, 128>>>(pts, W1);
    k_p1<<<PP/128, 128>>>(xyz, W1, b1, onx);
    k_st<<<dim3(16, 64), 256>>>(0);
    k_fin<<<1, 64>>>(g1, be1, 0);
    k_p2<<<PP/128, 128>>>(W2, b2);
    k_st<<<dim3(16, 64), 256>>>(1);
    k_fin<<<1, 64>>>(g2, be2, 1);
    k_p3<<<PP/128, 128>>>(W3, b3, ofe);
}

// round 14
// speedup vs baseline: 1.2063x; 1.2063x over previous
#include <cuda_runtime.h>

#define BB 8
#define NN 8192
#define NP 2048
#define KK 16
#define FF 64
#define PP (BB*NP*KK)
#define PTSN (BB*NN)
#define IINF 0x7fffffff
#define TILE 1024

typedef unsigned long long ull;
typedef unsigned int uint;

__device__ float g_Z1[(size_t)PTSN*FF];
__device__ float g_buf[(size_t)PP*FF];
__device__ int   g_fps[BB*NP];
__device__ int   g_knn[PP];
__device__ float g_stats[256];
__device__ float g_sc[256];

__global__ void k_zero() { g_stats[threadIdx.x] = 0.f; }

// ---- packed f32x2 helpers (per-lane IEEE rn, identical to scalar) ----
__device__ __forceinline__ ull pk2(float lo, float hi) {
    ull r; asm("mov.b64 %0, {%1,%2};" : "=l"(r) : "f"(lo), "f"(hi)); return r;
}
__device__ __forceinline__ void upk2(ull v, float& lo, float& hi) {
    asm("mov.b64 {%0,%1}, %2;" : "=f"(lo), "=f"(hi) : "l"(v));
}
__device__ __forceinline__ ull add2(ull a, ull b) {
    ull r; asm("add.rn.f32x2 %0, %1, %2;" : "=l"(r) : "l"(a), "l"(b)); return r;
}
__device__ __forceinline__ ull mul2(ull a, ull b) {
    ull r; asm("mul.rn.f32x2 %0, %1, %2;" : "=l"(r) : "l"(a), "l"(b)); return r;
}

// ---------------- FPS: one block per batch, 256 thr x 32 pts, REDUX reductions ----------------
__global__ __launch_bounds__(256) void k_fps(const float* __restrict__ xyz) {
    extern __shared__ float sm[];
    float* sx = sm; float* sy = sm + NN; float* sz = sm + 2*NN;
    uint* rvu = (uint*)(sm + 3*NN);     // 16 (double-buffered 2x8)
    int*  ri  = (int*)(rvu + 16);       // 16

    int b = blockIdx.x, tid = threadIdx.x, lane = tid & 31, wid = tid >> 5;
    int base = tid*32;
    const float* X = xyz + (size_t)b*3*NN;

    ull xp[16], yp[16], zp[16];
    float dmin[32];
    #pragma unroll
    for (int i = 0; i < 32; i += 4) {
        float4 vx = *(const float4*)(X + base + i);
        float4 vy = *(const float4*)(X + NN + base + i);
        float4 vz = *(const float4*)(X + 2*NN + base + i);
        xp[i/2]   = pk2(vx.x, vx.y); xp[i/2+1] = pk2(vx.z, vx.w);
        yp[i/2]   = pk2(vy.x, vy.y); yp[i/2+1] = pk2(vy.z, vy.w);
        zp[i/2]   = pk2(vz.x, vz.y); zp[i/2+1] = pk2(vz.z, vz.w);
        sx[base+i]=vx.x; sx[base+i+1]=vx.y; sx[base+i+2]=vx.z; sx[base+i+3]=vx.w;
        sy[base+i]=vy.x; sy[base+i+1]=vy.y; sy[base+i+2]=vy.z; sy[base+i+3]=vy.w;
        sz[base+i]=vz.x; sz[base+i+1]=vz.y; sz[base+i+2]=vz.z; sz[base+i+3]=vz.w;
    }
    #pragma unroll
    for (int i = 0; i < 32; i++) dmin[i] = 1e10f;

    float px = X[0], py = X[NN], pz = X[2*NN];
    if (tid == 0) g_fps[b*NP] = 0;
    __syncthreads();

    for (int t = 1; t < NP; t++) {
        ull npx = pk2(-px, -px), npy = pk2(-py, -py), npz = pk2(-pz, -pz);
        float bestv = 0.f; int besti = IINF;
        #pragma unroll
        for (int j = 0; j < 16; j++) {
            ull dx = add2(xp[j], npx);
            ull dy = add2(yp[j], npy);
            ull dz = add2(zp[j], npz);
            ull d2 = add2(add2(mul2(dx,dx), mul2(dy,dy)), mul2(dz,dz));
            float d0, d1; upk2(d2, d0, d1);
            int i0 = 2*j, i1 = 2*j + 1;
            dmin[i0] = fminf(dmin[i0], d0);
            if (dmin[i0] > bestv) { bestv = dmin[i0]; besti = base + i0; }
            dmin[i1] = fminf(dmin[i1], d1);
            if (dmin[i1] > bestv) { bestv = dmin[i1]; besti = base + i1; }
        }
        // warp argmax via REDUX (dmin >= 0 so float bits order as u32; ties -> lowest index)
        uint u  = __float_as_uint(bestv);
        uint um = __reduce_max_sync(0xffffffffu, u);
        uint wini = __reduce_min_sync(0xffffffffu, (u == um) ? (uint)besti : (uint)IINF);
        int bufo = (t & 1)*8;
        if (lane == 0) { rvu[bufo + wid] = um; ri[bufo + wid] = (int)wini; }
        __syncthreads();
        uint u2 = (lane < 8) ? rvu[bufo + lane] : 0u;
        int  j2 = (lane < 8) ? ri[bufo + lane]  : IINF;
        uint um2 = __reduce_max_sync(0xffffffffu, u2);
        uint jw  = __reduce_min_sync(0xffffffffu, (u2 == um2) ? (uint)j2 : (uint)IINF);
        int win = (int)jw;
        px = sx[win]; py = sy[win]; pz = sz[win];
        if (tid == 0) g_fps[b*NP + t] = win;
    }
}

// ---------------- gather new_xyz ----------------
__global__ void k_nx(const float* __restrict__ xyz, float* __restrict__ out) {
    int i = blockIdx.x*256 + threadIdx.x;
    int b = i >> 11, q = i & 2047, n = g_fps[i];
    #pragma unroll
    for (int c = 0; c < 3; c++)
        out[((size_t)b*3 + c)*NP + q] = xyz[((size_t)b*3 + c)*NN + n];
}

// ---------------- KNN: warp top-32, float-threshold ballot, REDUX maintenance ----------------
__device__ __forceinline__ uint ordu(float d) {
    uint u = __float_as_uint(d);
    return u ^ (((uint)((int)u >> 31)) | 0x80000000u);
}
__device__ __forceinline__ float iordu(uint u) {
    uint v = (u & 0x80000000u) ? (u ^ 0x80000000u) : ~u;
    return __uint_as_float(v);
}

__global__ __launch_bounds__(256) void k_knn(const float* __restrict__ xyz) {
    __shared__ float4 s4[TILE];     // 16KB tile -> 8 blocks/SM residency
    int b = blockIdx.y, tid = threadIdx.x, lane = tid & 31, w = tid >> 5;
    const float* X = xyz + (size_t)b*3*NN;
    int q = blockIdx.x*8 + w;
    int qi = g_fps[b*NP + q];
    float qx = X[qi], qy = X[NN+qi], qz = X[2*NN+qi];
    float qq = __fadd_rn(__fadd_rn(__fmul_rn(qx,qx), __fmul_rn(qy,qy)), __fmul_rn(qz,qz));

    // load tile 0
    for (int j = tid; j < TILE; j += 256) {
        float xx = X[j], yy = X[NN+j], zz = X[2*NN+j];
        float r = __fadd_rn(__fadd_rn(__fmul_rn(xx,xx), __fmul_rn(yy,yy)), __fmul_rn(zz,zz));
        s4[j] = make_float4(xx, yy, zz, r);
    }
    __syncthreads();

    uint hu; int hj;
    uint um; int jm;
    int wlane; float wd;
    {   // init: first 32 candidates fill the held set exactly
        float4 c = s4[lane];
        float dot = __fadd_rn(__fadd_rn(__fmul_rn(qx,c.x), __fmul_rn(qy,c.y)), __fmul_rn(qz,c.z));
        float d = __fsub_rn(__fadd_rn(qq, c.w), __fmul_rn(2.0f, dot));
        hu = ordu(d); hj = lane;
        um = __reduce_max_sync(0xffffffffu, hu);
        jm = (int)__reduce_max_sync(0xffffffffu, (hu == um) ? (uint)hj : 0u);
        uint bal = __ballot_sync(0xffffffffu, hu == um && hj == jm);
        wlane = __ffs(bal) - 1;
        wd = iordu(um);
    }

    for (int tile = 0; tile < NN; tile += TILE) {
        if (tile) {
            __syncthreads();
            for (int j = tid; j < TILE; j += 256) {
                int g = tile + j;
                float xx = X[g], yy = X[NN+g], zz = X[2*NN+g];
                float r = __fadd_rn(__fadd_rn(__fmul_rn(xx,xx), __fmul_rn(yy,yy)), __fmul_rn(zz,zz));
                s4[j] = make_float4(xx, yy, zz, r);
            }
            __syncthreads();
        }
        for (int k = (tile == 0 ? 32 : 0); k < TILE; k += 32) {
            float4 c = s4[k + lane];
            float dot = __fadd_rn(__fadd_rn(__fmul_rn(qx,c.x), __fmul_rn(qy,c.y)), __fmul_rn(qz,c.z));
            float d = __fsub_rn(__fadd_rn(qq, c.w), __fmul_rn(2.0f, dot));
            uint m = __ballot_sync(0xffffffffu, d <= wd);
            while (m) {
                int src = __ffs(m) - 1; m &= m - 1;
                float cd = __shfl_sync(0xffffffffu, d, src);
                int cj = tile + k + src;
                uint cu = ordu(cd);
                if (cu < um || (cu == um && cj < jm)) {
                    if (lane == wlane) { hu = cu; hj = cj; }
                    um = __reduce_max_sync(0xffffffffu, hu);
                    jm = (int)__reduce_max_sync(0xffffffffu, (hu == um) ? (uint)hj : 0u);
                    uint bal = __ballot_sync(0xffffffffu, hu == um && hj == jm);
                    wlane = __ffs(bal) - 1;
                    wd = iordu(um);
                }
            }
        }
    }
    int outidx = 0;
    #pragma unroll
    for (int r = 0; r < KK; r++) {
        uint mu = __reduce_min_sync(0xffffffffu, hu);
        uint mj = __reduce_min_sync(0xffffffffu, (hu == mu) ? (uint)hj : (uint)IINF);
        if (lane == r) outidx = (int)mj;
        if (hu == mu && hj == (int)mj) { hu = 0xffffffffu; hj = IINF; }
    }
    if (lane < KK) g_knn[((size_t)b*NP + q)*KK + lane] = outidx;
}

// ---------------- Z1 = W1[:,3:] @ points, per point ----------------
__global__ __launch_bounds__(128) void k_z1(const float* __restrict__ pts,
                                            const float* __restrict__ W1) {
    __shared__ float w[FF*FF];
    int tid = threadIdx.x;
    for (int i = tid; i < FF*FF; i += 128) w[i] = W1[(i>>6)*67 + 3 + (i&63)];
    __syncthreads();
    int p = blockIdx.x*128 + tid;
    int b = p >> 13, n = p & (NN-1);
    float xv[FF];
    #pragma unroll
    for (int f = 0; f < FF; f++) xv[f] = pts[((size_t)b*FF + f)*NN + n];
    float* zr = g_Z1 + (size_t)p*FF;
    for (int o = 0; o < FF; o += 4) {
        float a0=0.f, a1=0.f, a2=0.f, a3=0.f;
        #pragma unroll
        for (int f = 0; f < FF; f++) {
            float xf = xv[f];
            a0 = fmaf(w[(o+0)*FF+f], xf, a0);
            a1 = fmaf(w[(o+1)*FF+f], xf, a1);
            a2 = fmaf(w[(o+2)*FF+f], xf, a2);
            a3 = fmaf(w[(o+3)*FF+f], xf, a3);
        }
        *(float4*)(zr + o) = make_float4(a0, a1, a2, a3);
    }
}

// ---------------- pass1: y1 -> g_buf channel-major ----------------
__global__ __launch_bounds__(128) void k_p1(const float* __restrict__ xyz,
                                            const float* __restrict__ W1,
                                            const float* __restrict__ b1,
                                            const float* __restrict__ nxyz) {
    __shared__ float w0[64], w1s[64], w2s[64], bb[64];
    int tid = threadIdx.x;
    if (tid < 64) {
        w0[tid]  = W1[tid*67 + 0]; w1s[tid] = W1[tid*67 + 1];
        w2s[tid] = W1[tid*67 + 2]; bb[tid]  = b1[tid];
    }
    __syncthreads();
    int pos = blockIdx.x*128 + tid;
    int b = pos >> 15, q = (pos >> 4) & 2047, n = g_knn[pos];
    float cx = nxyz[((size_t)b*3+0)*NP+q], cy = nxyz[((size_t)b*3+1)*NP+q], cz = nxyz[((size_t)b*3+2)*NP+q];
    const float* X = xyz + (size_t)b*3*NN;
    float dx = X[n]-cx, dy = X[NN+n]-cy, dz = X[2*NN+n]-cz;
    const float4* zr = (const float4*)(g_Z1 + (size_t)(b*NN + n)*FF);
    #pragma unroll
    for (int i = 0; i < 16; i++) {
        float4 v = zr[i]; int o = 4*i;
        g_buf[(size_t)(o+0)*PP+pos] = fmaf(w2s[o+0],dz, fmaf(w1s[o+0],dy, fmaf(w0[o+0],dx, v.x+bb[o+0])));
        g_buf[(size_t)(o+1)*PP+pos] = fmaf(w2s[o+1],dz, fmaf(w1s[o+1],dy, fmaf(w0[o+1],dx, v.y+bb[o+1])));
        g_buf[(size_t)(o+2)*PP+pos] = fmaf(w2s[o+2],dz, fmaf(w1s[o+2],dy, fmaf(w0[o+2],dx, v.z+bb[o+2])));
        g_buf[(size_t)(o+3)*PP+pos] = fmaf(w2s[o+3],dz, fmaf(w1s[o+3],dy, fmaf(w0[o+3],dx, v.w+bb[o+3])));
    }
}

// ---------------- per-channel sum/sumsq ----------------
__global__ __launch_bounds__(256) void k_st(int which) {
    int o = blockIdx.y;
    const float* src = g_buf + (size_t)o*PP + blockIdx.x*(PP/16);
    float s = 0.f, s2 = 0.f;
    for (int i = threadIdx.x; i < PP/16; i += 256) {
        float v = src[i]; s += v; s2 = fmaf(v, v, s2);
    }
    #pragma unroll
    for (int off = 16; off; off >>= 1) {
        s  += __shfl_down_sync(0xffffffffu, s,  off);
        s2 += __shfl_down_sync(0xffffffffu, s2, off);
    }
    __shared__ float as[8], as2[8];
    int wid = threadIdx.x >> 5;
    if ((threadIdx.x & 31) == 0) { as[wid] = s; as2[wid] = s2; }
    __syncthreads();
    if (threadIdx.x == 0) {
        float ts = 0.f, ts2 = 0.f;
        #pragma unroll
        for (int w = 0; w < 8; w++) { ts += as[w]; ts2 += as2[w]; }
        atomicAdd(g_stats + which*128 + o, ts);
        atomicAdd(g_stats + which*128 + 64 + o, ts2);
    }
}

__global__ void k_fin(const float* __restrict__ gam, const float* __restrict__ bet, int which) {
    int o = threadIdx.x;
    float m = g_stats[which*128 + o] / (float)PP;
    float v = g_stats[which*128 + 64 + o] / (float)PP - m*m;
    v = fmaxf(v, 0.f);
    float sc = gam[o] * rsqrtf(v + 1e-5f);
    g_sc[which*128 + o] = sc;
    g_sc[which*128 + 64 + o] = bet[o] - m*sc;
}

// ---------------- pass2: bn1+relu -> conv2 (in place) ----------------
__global__ __launch_bounds__(128) void k_p2(const float* __restrict__ W2, const float* __restrict__ b2) {
    __shared__ float w[64*64];
    __shared__ float sc[64], sh[64], bb[64];
    int tid = threadIdx.x;
    for (int i = tid; i < 64*64; i += 128) w[i] = W2[i];
    if (tid < 64) { sc[tid] = g_sc[tid]; sh[tid] = g_sc[64+tid]; bb[tid] = b2[tid]; }
    __syncthreads();
    int pos = blockIdx.x*128 + tid;
    float h[64];
    #pragma unroll
    for (int o = 0; o < 64; o++) {
        float y = g_buf[(size_t)o*PP + pos];
        h[o] = fmaxf(fmaf(y, sc[o], sh[o]), 0.f);
    }
    for (int o = 0; o < 64; o++) {
        float a = bb[o];
        const float* wr = w + o*64;
        #pragma unroll
        for (int f = 0; f < 64; f++) a = fmaf(wr[f], h[f], a);
        g_buf[(size_t)o*PP + pos] = a;
    }
}

// ---------------- pass3: bn2+relu -> conv3 -> max over K ----------------
__global__ __launch_bounds__(128) void k_p3(const float* __restrict__ W3, const float* __restrict__ b3,
                                            float* __restrict__ outf) {
    __shared__ float w[128*64];
    __shared__ float sc[64], sh[64], bb[128];
    int tid = threadIdx.x;
    for (int i = tid; i < 128*64; i += 128) w[i] = W3[i];
    if (tid < 64) { sc[tid] = g_sc[128+tid]; sh[tid] = g_sc[192+tid]; }
    if (tid < 128) bb[tid] = b3[tid];
    __syncthreads();
    int pos = blockIdx.x*128 + tid;
    float h[64];
    #pragma unroll
    for (int o = 0; o < 64; o++) {
        float y = g_buf[(size_t)o*PP + pos];
        h[o] = fmaxf(fmaf(y, sc[o], sh[o]), 0.f);
    }
    int lane = tid & 15;
    int q = pos >> 4;
    int b = q >> 11, qq = q & 2047;
    for (int c = 0; c < 4; c++) {
        float acc[32];
        #pragma unroll
        for (int o = 0; o < 32; o++) {
            const float* wr = w + (c*32 + o)*64;
            float a = bb[c*32 + o];
            #pragma unroll
            for (int f = 0; f < 64; f++) a = fmaf(wr[f], h[f], a);
            acc[o] = a;
        }
        #pragma unroll
        for (int o = 0; o < 32; o++) {
            float v = acc[o];
            #pragma unroll
            for (int off = 1; off < 16; off <<= 1)
                v = fmaxf(v, __shfl_xor_sync(0xffffffffu, v, off));
            acc[o] = v;
        }
        #pragma unroll
        for (int o = 0; o < 32; o++)
            if ((o & 15) == lane)
                outf[((size_t)b*128 + c*32 + o)*NP + qq] = acc[o];
    }
}

extern "C" void kernel_launch(void* const* d_in, const int* in_sizes, int n_in,
                              void* d_out, int out_size) {
    const float* xyz = (const float*)d_in[0];
    const float* pts = (const float*)d_in[1];
    const float* W1  = (const float*)d_in[2];
    const float* b1  = (const float*)d_in[3];
    const float* g1  = (const float*)d_in[4];
    const float* be1 = (const float*)d_in[5];
    const float* W2  = (const float*)d_in[6];
    const float* b2  = (const float*)d_in[7];
    const float* g2  = (const float*)d_in[8];
    const float* be2 = (const float*)d_in[9];
    const float* W3  = (const float*)d_in[10];
    const float* b3  = (const float*)d_in[11];
    float* out  = (float*)d_out;
    float* onx  = out;                       // new_xyz (B,3,NP)
    float* ofe  = out + (size_t)BB*3*NP;     // new_feat (B,128,NP)

    static cudaStream_t s_side = nullptr;
    static cudaEvent_t ev_fork = nullptr, ev_join = nullptr;
    if (!s_side) {
        cudaStreamCreateWithFlags(&s_side, cudaStreamNonBlocking);
        cudaEventCreateWithFlags(&ev_fork, cudaEventDisableTiming);
        cudaEventCreateWithFlags(&ev_join, cudaEventDisableTiming);
    }

    const int FPS_SM = (3*NN + 32)*4;
    cudaFuncSetAttribute(k_fps, cudaFuncAttributeMaxDynamicSharedMemorySize, FPS_SM);

    // fork: z1 + stats-zero run on idle SMs concurrently with FPS (no dependence)
    cudaEventRecord(ev_fork, 0);
    cudaStreamWaitEvent(s_side, ev_fork, 0);
    k_zero<<<1, 256, 0, s_side>>>();
    k_z1<<<PTSN/128, 128, 0, s_side>>>(pts, W1);
    cudaEventRecord(ev_join, s_side);

    k_fps<<<BB, 256, FPS_SM>>>(xyz);
    k_nx<<<(BB*NP)/256, 256>>>(xyz, onx);
    k_knn<<<dim3(NP/8, BB), 256>>>(xyz);

    // join before p1 (needs g_Z1 + zeroed g_stats + g_knn)
    cudaStreamWaitEvent(0, ev_join, 0);
    k_p1<<<PP/128, 128>>>(xyz, W1, b1, onx);
    k_st<<<dim3(16, 64), 256>>>(0);
    k_fin<<<1, 64>>>(g1, be1, 0);
    k_p2<<<PP/128, 128>>>(W2, b2);
    k_st<<<dim3(16, 64), 256>>>(1);
    k_fin<<<1, 64>>>(g2, be2, 1);
    k_p3<<<PP/128, 128>>>(W3, b3, ofe);
}

// round 15
// speedup vs baseline: 1.2459x; 1.0328x over previous
#include <cuda_runtime.h>

#define BB 8
#define NN 8192
#define NP 2048
#define KK 16
#define FF 64
#define PP (BB*NP*KK)
#define PTSN (BB*NN)
#define IINF 0x7fffffff
#define TILE 1024

typedef unsigned long long ull;
typedef unsigned int uint;

__device__ float g_Z1[(size_t)PTSN*FF];
__device__ float g_buf[(size_t)PP*FF];
__device__ int   g_fps[BB*NP];
__device__ int   g_knn[PP];
__device__ float g_stats[256];
__device__ float g_sc[256];
__device__ int   g_prog[BB];

__global__ void k_zero() {
    g_stats[threadIdx.x] = 0.f;
    if (threadIdx.x < BB) g_prog[threadIdx.x] = 0;
}

// ---- packed f32x2 helpers (per-lane IEEE rn, identical to scalar) ----
__device__ __forceinline__ ull pk2(float lo, float hi) {
    ull r; asm("mov.b64 %0, {%1,%2};" : "=l"(r) : "f"(lo), "f"(hi)); return r;
}
__device__ __forceinline__ void upk2(ull v, float& lo, float& hi) {
    asm("mov.b64 {%0,%1}, %2;" : "=f"(lo), "=f"(hi) : "l"(v));
}
__device__ __forceinline__ ull add2(ull a, ull b) {
    ull r; asm("add.rn.f32x2 %0, %1, %2;" : "=l"(r) : "l"(a), "l"(b)); return r;
}
__device__ __forceinline__ ull mul2(ull a, ull b) {
    ull r; asm("mul.rn.f32x2 %0, %1, %2;" : "=l"(r) : "l"(a), "l"(b)); return r;
}

__device__ __forceinline__ uint ordu(float d) {
    uint u = __float_as_uint(d);
    return u ^ (((uint)((int)u >> 31)) | 0x80000000u);
}
__device__ __forceinline__ float iordu(uint u) {
    uint v = (u & 0x80000000u) ? (u ^ 0x80000000u) : ~u;
    return __uint_as_float(v);
}

// ---------------- fused FPS (blocks 0..7) + self-pacing KNN (blocks 8..2055) ----------------
__global__ __launch_bounds__(256) void k_fused(const float* __restrict__ xyz) {
    extern __shared__ float sm[];
    int tid = threadIdx.x, lane = tid & 31, wid = tid >> 5;

    if (blockIdx.x < 8) {
        // ================= FPS role =================
        float* sx = sm; float* sy = sm + NN; float* sz = sm + 2*NN;
        uint* rvu = (uint*)(sm + 3*NN);     // 16 (double-buffered 2x8)
        int*  ri  = (int*)(rvu + 16);       // 16

        int b = blockIdx.x;
        int base = tid*32;
        const float* X = xyz + (size_t)b*3*NN;

        ull xp[16], yp[16], zp[16];
        float dmin[32];
        #pragma unroll
        for (int i = 0; i < 32; i += 4) {
            float4 vx = *(const float4*)(X + base + i);
            float4 vy = *(const float4*)(X + NN + base + i);
            float4 vz = *(const float4*)(X + 2*NN + base + i);
            xp[i/2]   = pk2(vx.x, vx.y); xp[i/2+1] = pk2(vx.z, vx.w);
            yp[i/2]   = pk2(vy.x, vy.y); yp[i/2+1] = pk2(vy.z, vy.w);
            zp[i/2]   = pk2(vz.x, vz.y); zp[i/2+1] = pk2(vz.z, vz.w);
            sx[base+i]=vx.x; sx[base+i+1]=vx.y; sx[base+i+2]=vx.z; sx[base+i+3]=vx.w;
            sy[base+i]=vy.x; sy[base+i+1]=vy.y; sy[base+i+2]=vy.z; sy[base+i+3]=vy.w;
            sz[base+i]=vz.x; sz[base+i+1]=vz.y; sz[base+i+2]=vz.z; sz[base+i+3]=vz.w;
        }
        #pragma unroll
        for (int i = 0; i < 32; i++) dmin[i] = 1e10f;

        float px = X[0], py = X[NN], pz = X[2*NN];
        if (tid == 0) g_fps[b*NP] = 0;
        __syncthreads();

        for (int t = 1; t < NP; t++) {
            ull npx = pk2(-px, -px), npy = pk2(-py, -py), npz = pk2(-pz, -pz);
            float bestv = 0.f; int besti = IINF;
            #pragma unroll
            for (int j = 0; j < 16; j++) {
                ull dx = add2(xp[j], npx);
                ull dy = add2(yp[j], npy);
                ull dz = add2(zp[j], npz);
                ull d2 = add2(add2(mul2(dx,dx), mul2(dy,dy)), mul2(dz,dz));
                float d0, d1; upk2(d2, d0, d1);
                int i0 = 2*j, i1 = 2*j + 1;
                dmin[i0] = fminf(dmin[i0], d0);
                if (dmin[i0] > bestv) { bestv = dmin[i0]; besti = base + i0; }
                dmin[i1] = fminf(dmin[i1], d1);
                if (dmin[i1] > bestv) { bestv = dmin[i1]; besti = base + i1; }
            }
            uint u  = __float_as_uint(bestv);
            uint um = __reduce_max_sync(0xffffffffu, u);
            uint wini = __reduce_min_sync(0xffffffffu, (u == um) ? (uint)besti : (uint)IINF);
            int bufo = (t & 1)*8;
            if (lane == 0) { rvu[bufo + wid] = um; ri[bufo + wid] = (int)wini; }
            __syncthreads();
            uint u2 = (lane < 8) ? rvu[bufo + lane] : 0u;
            int  j2 = (lane < 8) ? ri[bufo + lane]  : IINF;
            uint um2 = __reduce_max_sync(0xffffffffu, u2);
            uint jw  = __reduce_min_sync(0xffffffffu, (u2 == um2) ? (uint)j2 : (uint)IINF);
            int win = (int)jw;
            px = sx[win]; py = sy[win]; pz = sz[win];
            if (tid == 0) {
                g_fps[b*NP + t] = win;
                if ((t & 7) == 0 || t == NP-1) {
                    __threadfence();
                    *(volatile int*)&g_prog[b] = t;
                }
            }
        }
    } else {
        // ================= KNN role (self-pacing consumer) =================
        float4* s4 = (float4*)sm;           // 16KB tile
        int kid = blockIdx.x - 8;
        int x = kid >> 3, b = kid & 7;
        const float* X = xyz + (size_t)b*3*NN;

        // load tile 0 while (possibly) waiting on the producer
        for (int j = tid; j < TILE; j += 256) {
            float xx = X[j], yy = X[NN+j], zz = X[2*NN+j];
            float r = __fadd_rn(__fadd_rn(__fmul_rn(xx,xx), __fmul_rn(yy,yy)), __fmul_rn(zz,zz));
            s4[j] = make_float4(xx, yy, zz, r);
        }
        if (tid == 0) {
            int qmax = x*8 + 7;
            while (*(volatile int*)&g_prog[b] < qmax) __nanosleep(128);
            __threadfence();
        }
        __syncthreads();

        int q = x*8 + wid;
        int qi = g_fps[b*NP + q];
        float qx = X[qi], qy = X[NN+qi], qz = X[2*NN+qi];
        float qq = __fadd_rn(__fadd_rn(__fmul_rn(qx,qx), __fmul_rn(qy,qy)), __fmul_rn(qz,qz));

        uint hu; int hj;
        uint um; int jm;
        int wlane; float wd;
        {
            float4 c = s4[lane];
            float dot = __fadd_rn(__fadd_rn(__fmul_rn(qx,c.x), __fmul_rn(qy,c.y)), __fmul_rn(qz,c.z));
            float d = __fsub_rn(__fadd_rn(qq, c.w), __fmul_rn(2.0f, dot));
            hu = ordu(d); hj = lane;
            um = __reduce_max_sync(0xffffffffu, hu);
            jm = (int)__reduce_max_sync(0xffffffffu, (hu == um) ? (uint)hj : 0u);
            uint bal = __ballot_sync(0xffffffffu, hu == um && hj == jm);
            wlane = __ffs(bal) - 1;
            wd = iordu(um);
        }

        for (int tile = 0; tile < NN; tile += TILE) {
            if (tile) {
                __syncthreads();
                for (int j = tid; j < TILE; j += 256) {
                    int g = tile + j;
                    float xx = X[g], yy = X[NN+g], zz = X[2*NN+g];
                    float r = __fadd_rn(__fadd_rn(__fmul_rn(xx,xx), __fmul_rn(yy,yy)), __fmul_rn(zz,zz));
                    s4[j] = make_float4(xx, yy, zz, r);
                }
                __syncthreads();
            }
            for (int k = (tile == 0 ? 32 : 0); k < TILE; k += 32) {
                float4 c = s4[k + lane];
                float dot = __fadd_rn(__fadd_rn(__fmul_rn(qx,c.x), __fmul_rn(qy,c.y)), __fmul_rn(qz,c.z));
                float d = __fsub_rn(__fadd_rn(qq, c.w), __fmul_rn(2.0f, dot));
                uint m = __ballot_sync(0xffffffffu, d <= wd);
                while (m) {
                    int src = __ffs(m) - 1; m &= m - 1;
                    float cd = __shfl_sync(0xffffffffu, d, src);
                    int cj = tile + k + src;
                    uint cu = ordu(cd);
                    if (cu < um || (cu == um && cj < jm)) {
                        if (lane == wlane) { hu = cu; hj = cj; }
                        um = __reduce_max_sync(0xffffffffu, hu);
                        jm = (int)__reduce_max_sync(0xffffffffu, (hu == um) ? (uint)hj : 0u);
                        uint bal = __ballot_sync(0xffffffffu, hu == um && hj == jm);
                        wlane = __ffs(bal) - 1;
                        wd = iordu(um);
                    }
                }
            }
        }
        int outidx = 0;
        #pragma unroll
        for (int r = 0; r < KK; r++) {
            uint mu = __reduce_min_sync(0xffffffffu, hu);
            uint mj = __reduce_min_sync(0xffffffffu, (hu == mu) ? (uint)hj : (uint)IINF);
            if (lane == r) outidx = (int)mj;
            if (hu == mu && hj == (int)mj) { hu = 0xffffffffu; hj = IINF; }
        }
        if (lane < KK) g_knn[((size_t)b*NP + q)*KK + lane] = outidx;
    }
}

// ---------------- gather new_xyz ----------------
__global__ void k_nx(const float* __restrict__ xyz, float* __restrict__ out) {
    int i = blockIdx.x*256 + threadIdx.x;
    int b = i >> 11, q = i & 2047, n = g_fps[i];
    #pragma unroll
    for (int c = 0; c < 3; c++)
        out[((size_t)b*3 + c)*NP + q] = xyz[((size_t)b*3 + c)*NN + n];
}

// ---------------- Z1 = W1[:,3:] @ points, per point ----------------
__global__ __launch_bounds__(128) void k_z1(const float* __restrict__ pts,
                                            const float* __restrict__ W1) {
    __shared__ float w[FF*FF];
    int tid = threadIdx.x;
    for (int i = tid; i < FF*FF; i += 128) w[i] = W1[(i>>6)*67 + 3 + (i&63)];
    __syncthreads();
    int p = blockIdx.x*128 + tid;
    int b = p >> 13, n = p & (NN-1);
    float xv[FF];
    #pragma unroll
    for (int f = 0; f < FF; f++) xv[f] = pts[((size_t)b*FF + f)*NN + n];
    float* zr = g_Z1 + (size_t)p*FF;
    for (int o = 0; o < FF; o += 4) {
        float a0=0.f, a1=0.f, a2=0.f, a3=0.f;
        #pragma unroll
        for (int f = 0; f < FF; f++) {
            float xf = xv[f];
            a0 = fmaf(w[(o+0)*FF+f], xf, a0);
            a1 = fmaf(w[(o+1)*FF+f], xf, a1);
            a2 = fmaf(w[(o+2)*FF+f], xf, a2);
            a3 = fmaf(w[(o+3)*FF+f], xf, a3);
        }
        *(float4*)(zr + o) = make_float4(a0, a1, a2, a3);
    }
}

// ---------------- pass1: y1 -> g_buf channel-major ----------------
__global__ __launch_bounds__(128) void k_p1(const float* __restrict__ xyz,
                                            const float* __restrict__ W1,
                                            const float* __restrict__ b1,
                                            const float* __restrict__ nxyz) {
    __shared__ float w0[64], w1s[64], w2s[64], bb[64];
    int tid = threadIdx.x;
    if (tid < 64) {
        w0[tid]  = W1[tid*67 + 0]; w1s[tid] = W1[tid*67 + 1];
        w2s[tid] = W1[tid*67 + 2]; bb[tid]  = b1[tid];
    }
    __syncthreads();
    int pos = blockIdx.x*128 + tid;
    int b = pos >> 15, q = (pos >> 4) & 2047, n = g_knn[pos];
    float cx = nxyz[((size_t)b*3+0)*NP+q], cy = nxyz[((size_t)b*3+1)*NP+q], cz = nxyz[((size_t)b*3+2)*NP+q];
    const float* X = xyz + (size_t)b*3*NN;
    float dx = X[n]-cx, dy = X[NN+n]-cy, dz = X[2*NN+n]-cz;
    const float4* zr = (const float4*)(g_Z1 + (size_t)(b*NN + n)*FF);
    #pragma unroll
    for (int i = 0; i < 16; i++) {
        float4 v = zr[i]; int o = 4*i;
        g_buf[(size_t)(o+0)*PP+pos] = fmaf(w2s[o+0],dz, fmaf(w1s[o+0],dy, fmaf(w0[o+0],dx, v.x+bb[o+0])));
        g_buf[(size_t)(o+1)*PP+pos] = fmaf(w2s[o+1],dz, fmaf(w1s[o+1],dy, fmaf(w0[o+1],dx, v.y+bb[o+1])));
        g_buf[(size_t)(o+2)*PP+pos] = fmaf(w2s[o+2],dz, fmaf(w1s[o+2],dy, fmaf(w0[o+2],dx, v.z+bb[o+2])));
        g_buf[(size_t)(o+3)*PP+pos] = fmaf(w2s[o+3],dz, fmaf(w1s[o+3],dy, fmaf(w0[o+3],dx, v.w+bb[o+3])));
    }
}

// ---------------- per-channel sum/sumsq ----------------
__global__ __launch_bounds__(256) void k_st(int which) {
    int o = blockIdx.y;
    const float* src = g_buf + (size_t)o*PP + blockIdx.x*(PP/16);
    float s = 0.f, s2 = 0.f;
    for (int i = threadIdx.x; i < PP/16; i += 256) {
        float v = src[i]; s += v; s2 = fmaf(v, v, s2);
    }
    #pragma unroll
    for (int off = 16; off; off >>= 1) {
        s  += __shfl_down_sync(0xffffffffu, s,  off);
        s2 += __shfl_down_sync(0xffffffffu, s2, off);
    }
    __shared__ float as[8], as2[8];
    int wid = threadIdx.x >> 5;
    if ((threadIdx.x & 31) == 0) { as[wid] = s; as2[wid] = s2; }
    __syncthreads();
    if (threadIdx.x == 0) {
        float ts = 0.f, ts2 = 0.f;
        #pragma unroll
        for (int w = 0; w < 8; w++) { ts += as[w]; ts2 += as2[w]; }
        atomicAdd(g_stats + which*128 + o, ts);
        atomicAdd(g_stats + which*128 + 64 + o, ts2);
    }
}

__global__ void k_fin(const float* __restrict__ gam, const float* __restrict__ bet, int which) {
    int o = threadIdx.x;
    float m = g_stats[which*128 + o] / (float)PP;
    float v = g_stats[which*128 + 64 + o] / (float)PP - m*m;
    v = fmaxf(v, 0.f);
    float sc = gam[o] * rsqrtf(v + 1e-5f);
    g_sc[which*128 + o] = sc;
    g_sc[which*128 + 64 + o] = bet[o] - m*sc;
}

// ---------------- pass2: bn1+relu -> conv2 (in place) ----------------
__global__ __launch_bounds__(128) void k_p2(const float* __restrict__ W2, const float* __restrict__ b2) {
    __shared__ float w[64*64];
    __shared__ float sc[64], sh[64], bb[64];
    int tid = threadIdx.x;
    for (int i = tid; i < 64*64; i += 128) w[i] = W2[i];
    if (tid < 64) { sc[tid] = g_sc[tid]; sh[tid] = g_sc[64+tid]; bb[tid] = b2[tid]; }
    __syncthreads();
    int pos = blockIdx.x*128 + tid;
    float h[64];
    #pragma unroll
    for (int o = 0; o < 64; o++) {
        float y = g_buf[(size_t)o*PP + pos];
        h[o] = fmaxf(fmaf(y, sc[o], sh[o]), 0.f);
    }
    for (int o = 0; o < 64; o++) {
        float a = bb[o];
        const float* wr = w + o*64;
        #pragma unroll
        for (int f = 0; f < 64; f++) a = fmaf(wr[f], h[f], a);
        g_buf[(size_t)o*PP + pos] = a;
    }
}

// ---------------- pass3: bn2+relu -> conv3 -> max over K ----------------
__global__ __launch_bounds__(128) void k_p3(const float* __restrict__ W3, const float* __restrict__ b3,
                                            float* __restrict__ outf) {
    __shared__ float w[128*64];
    __shared__ float sc[64], sh[64], bb[128];
    int tid = threadIdx.x;
    for (int i = tid; i < 128*64; i += 128) w[i] = W3[i];
    if (tid < 64) { sc[tid] = g_sc[128+tid]; sh[tid] = g_sc[192+tid]; }
    if (tid < 128) bb[tid] = b3[tid];
    __syncthreads();
    int pos = blockIdx.x*128 + tid;
    float h[64];
    #pragma unroll
    for (int o = 0; o < 64; o++) {
        float y = g_buf[(size_t)o*PP + pos];
        h[o] = fmaxf(fmaf(y, sc[o], sh[o]), 0.f);
    }
    int lane = tid & 15;
    int q = pos >> 4;
    int b = q >> 11, qq = q & 2047;
    for (int c = 0; c < 4; c++) {
        float acc[32];
        #pragma unroll
        for (int o = 0; o < 32; o++) {
            const float* wr = w + (c*32 + o)*64;
            float a = bb[c*32 + o];
            #pragma unroll
            for (int f = 0; f < 64; f++) a = fmaf(wr[f], h[f], a);
            acc[o] = a;
        }
        #pragma unroll
        for (int o = 0; o < 32; o++) {
            float v = acc[o];
            #pragma unroll
            for (int off = 1; off < 16; off <<= 1)
                v = fmaxf(v, __shfl_xor_sync(0xffffffffu, v, off));
            acc[o] = v;
        }
        #pragma unroll
        for (int o = 0; o < 32; o++)
            if ((o & 15) == lane)
                outf[((size_t)b*128 + c*32 + o)*NP + qq] = acc[o];
    }
}

extern "C" void kernel_launch(void* const* d_in, const int* in_sizes, int n_in,
                              void* d_out, int out_size) {
    const float* xyz = (const float*)d_in[0];
    const float* pts = (const float*)d_in[1];
    const float* W1  = (const float*)d_in[2];
    const float* b1  = (const float*)d_in[3];
    const float* g1  = (const float*)d_in[4];
    const float* be1 = (const float*)d_in[5];
    const float* W2  = (const float*)d_in[6];
    const float* b2  = (const float*)d_in[7];
    const float* g2  = (const float*)d_in[8];
    const float* be2 = (const float*)d_in[9];
    const float* W3  = (const float*)d_in[10];
    const float* b3  = (const float*)d_in[11];
    float* out  = (float*)d_out;
    float* onx  = out;                       // new_xyz (B,3,NP)
    float* ofe  = out + (size_t)BB*3*NP;     // new_feat (B,128,NP)

    static cudaStream_t s_side = nullptr;
    static cudaEvent_t ev_fork = nullptr, ev_join = nullptr;
    if (!s_side) {
        cudaStreamCreateWithFlags(&s_side, cudaStreamNonBlocking);
        cudaEventCreateWithFlags(&ev_fork, cudaEventDisableTiming);
        cudaEventCreateWithFlags(&ev_join, cudaEventDisableTiming);
    }

    const int FPS_SM = (3*NN + 32)*4;
    cudaFuncSetAttribute(k_fused, cudaFuncAttributeMaxDynamicSharedMemorySize, FPS_SM);

    // fork: z1 runs on idle SMs concurrently with the fused producer/consumer kernel
    cudaEventRecord(ev_fork, 0);
    cudaStreamWaitEvent(s_side, ev_fork, 0);
    k_z1<<<PTSN/128, 128, 0, s_side>>>(pts, W1);
    cudaEventRecord(ev_join, s_side);

    k_zero<<<1, 256>>>();                               // zero stats + progress flags
    k_fused<<<8 + BB*(NP/8), 256, FPS_SM>>>(xyz);       // FPS + overlapped KNN
    k_nx<<<(BB*NP)/256, 256>>>(xyz, onx);

    // join before p1 (needs g_Z1 + zeroed g_stats + g_knn)
    cudaStreamWaitEvent(0, ev_join, 0);
    k_p1<<<PP/128, 128>>>(xyz, W1, b1, onx);
    k_st<<<dim3(16, 64), 256>>>(0);
    k_fin<<<1, 64>>>(g1, be1, 0);
    k_p2<<<PP/128, 128>>>(W2, b2);
    k_st<<<dim3(16, 64), 256>>>(1);
    k_fin<<<1, 64>>>(g2, be2, 1);
    k_p3<<<PP/128, 128>>>(W3, b3, ofe);
}

// round 16
// speedup vs baseline: 1.2750x; 1.0234x over previous
#include <cuda_runtime.h>

#define BB 8
#define NN 8192
#define NP 2048
#define KK 16
#define FF 64
#define PP (BB*NP*KK)
#define PTSN (BB*NN)
#define IINF 0x7fffffff
#define TILE 1024

typedef unsigned long long ull;
typedef unsigned int uint;

__device__ float g_Z1[(size_t)PTSN*FF];
__device__ float g_buf[(size_t)PP*FF];
__device__ int   g_fps[BB*NP];
__device__ int   g_knn[PP];
__device__ float g_stats[256];
__device__ float g_sc[256];
__device__ int   g_prog[BB];

__global__ void k_zero() {
    g_stats[threadIdx.x] = 0.f;
    if (threadIdx.x < BB) g_prog[threadIdx.x] = 0;
}

// ---- packed f32x2 helpers (per-lane IEEE rn, identical to scalar) ----
__device__ __forceinline__ ull pk2(float lo, float hi) {
    ull r; asm("mov.b64 %0, {%1,%2};" : "=l"(r) : "f"(lo), "f"(hi)); return r;
}
__device__ __forceinline__ void upk2(ull v, float& lo, float& hi) {
    asm("mov.b64 {%0,%1}, %2;" : "=f"(lo), "=f"(hi) : "l"(v));
}
__device__ __forceinline__ ull add2(ull a, ull b) {
    ull r; asm("add.rn.f32x2 %0, %1, %2;" : "=l"(r) : "l"(a), "l"(b)); return r;
}
__device__ __forceinline__ ull mul2(ull a, ull b) {
    ull r; asm("mul.rn.f32x2 %0, %1, %2;" : "=l"(r) : "l"(a), "l"(b)); return r;
}

__device__ __forceinline__ uint ordu(float d) {
    uint u = __float_as_uint(d);
    return u ^ (((uint)((int)u >> 31)) | 0x80000000u);
}
__device__ __forceinline__ float iordu(uint u) {
    uint v = (u & 0x80000000u) ? (u ^ 0x80000000u) : ~u;
    return __uint_as_float(v);
}

// ---------------- FPS producer: one block/batch, publishes progress ----------------
__global__ __launch_bounds__(256) void k_fps(const float* __restrict__ xyz) {
    extern __shared__ float sm[];
    float* sx = sm; float* sy = sm + NN; float* sz = sm + 2*NN;
    uint* rvu = (uint*)(sm + 3*NN);     // 16 (double-buffered 2x8)
    int*  ri  = (int*)(rvu + 16);       // 16

    int b = blockIdx.x, tid = threadIdx.x, lane = tid & 31, wid = tid >> 5;
    int base = tid*32;
    const float* X = xyz + (size_t)b*3*NN;

    ull xp[16], yp[16], zp[16];
    float dmin[32];
    #pragma unroll
    for (int i = 0; i < 32; i += 4) {
        float4 vx = *(const float4*)(X + base + i);
        float4 vy = *(const float4*)(X + NN + base + i);
        float4 vz = *(const float4*)(X + 2*NN + base + i);
        xp[i/2]   = pk2(vx.x, vx.y); xp[i/2+1] = pk2(vx.z, vx.w);
        yp[i/2]   = pk2(vy.x, vy.y); yp[i/2+1] = pk2(vy.z, vy.w);
        zp[i/2]   = pk2(vz.x, vz.y); zp[i/2+1] = pk2(vz.z, vz.w);
        sx[base+i]=vx.x; sx[base+i+1]=vx.y; sx[base+i+2]=vx.z; sx[base+i+3]=vx.w;
        sy[base+i]=vy.x; sy[base+i+1]=vy.y; sy[base+i+2]=vy.z; sy[base+i+3]=vy.w;
        sz[base+i]=vz.x; sz[base+i+1]=vz.y; sz[base+i+2]=vz.z; sz[base+i+3]=vz.w;
    }
    #pragma unroll
    for (int i = 0; i < 32; i++) dmin[i] = 1e10f;

    float px = X[0], py = X[NN], pz = X[2*NN];
    if (tid == 0) g_fps[b*NP] = 0;
    __syncthreads();

    for (int t = 1; t < NP; t++) {
        ull npx = pk2(-px, -px), npy = pk2(-py, -py), npz = pk2(-pz, -pz);
        float bestv = 0.f; int besti = IINF;
        #pragma unroll
        for (int j = 0; j < 16; j++) {
            ull dx = add2(xp[j], npx);
            ull dy = add2(yp[j], npy);
            ull dz = add2(zp[j], npz);
            ull d2 = add2(add2(mul2(dx,dx), mul2(dy,dy)), mul2(dz,dz));
            float d0, d1; upk2(d2, d0, d1);
            int i0 = 2*j, i1 = 2*j + 1;
            dmin[i0] = fminf(dmin[i0], d0);
            if (dmin[i0] > bestv) { bestv = dmin[i0]; besti = base + i0; }
            dmin[i1] = fminf(dmin[i1], d1);
            if (dmin[i1] > bestv) { bestv = dmin[i1]; besti = base + i1; }
        }
        uint u  = __float_as_uint(bestv);
        uint um = __reduce_max_sync(0xffffffffu, u);
        uint wini = __reduce_min_sync(0xffffffffu, (u == um) ? (uint)besti : (uint)IINF);
        int bufo = (t & 1)*8;
        if (lane == 0) { rvu[bufo + wid] = um; ri[bufo + wid] = (int)wini; }
        __syncthreads();
        uint u2 = (lane < 8) ? rvu[bufo + lane] : 0u;
        int  j2 = (lane < 8) ? ri[bufo + lane]  : IINF;
        uint um2 = __reduce_max_sync(0xffffffffu, u2);
        uint jw  = __reduce_min_sync(0xffffffffu, (u2 == um2) ? (uint)j2 : (uint)IINF);
        int win = (int)jw;
        px = sx[win]; py = sy[win]; pz = sz[win];
        if (tid == 0) {
            g_fps[b*NP + t] = win;
            if ((t & 7) == 0 || t == NP-1) {
                __threadfence();
                *(volatile int*)&g_prog[b] = t;
            }
        }
    }
}

// ---------------- KNN consumer: self-pacing on g_prog, 16KB static smem ----------------
__global__ __launch_bounds__(256) void k_knn(const float* __restrict__ xyz) {
    __shared__ float4 s4[TILE];
    int tid = threadIdx.x, lane = tid & 31, wid = tid >> 5;
    int x = blockIdx.x, b = blockIdx.y;
    const float* X = xyz + (size_t)b*3*NN;

    // load tile 0 while (possibly) waiting on the producer
    for (int j = tid; j < TILE; j += 256) {
        float xx = X[j], yy = X[NN+j], zz = X[2*NN+j];
        float r = __fadd_rn(__fadd_rn(__fmul_rn(xx,xx), __fmul_rn(yy,yy)), __fmul_rn(zz,zz));
        s4[j] = make_float4(xx, yy, zz, r);
    }
    if (tid == 0) {
        int qmax = x*8 + 7;
        while (*(volatile int*)&g_prog[b] < qmax) __nanosleep(128);
        __threadfence();
    }
    __syncthreads();

    int q = x*8 + wid;
    int qi = g_fps[b*NP + q];
    float qx = X[qi], qy = X[NN+qi], qz = X[2*NN+qi];
    float qq = __fadd_rn(__fadd_rn(__fmul_rn(qx,qx), __fmul_rn(qy,qy)), __fmul_rn(qz,qz));

    uint hu; int hj;
    uint um; int jm;
    int wlane; float wd;
    {
        float4 c = s4[lane];
        float dot = __fadd_rn(__fadd_rn(__fmul_rn(qx,c.x), __fmul_rn(qy,c.y)), __fmul_rn(qz,c.z));
        float d = __fsub_rn(__fadd_rn(qq, c.w), __fmul_rn(2.0f, dot));
        hu = ordu(d); hj = lane;
        um = __reduce_max_sync(0xffffffffu, hu);
        jm = (int)__reduce_max_sync(0xffffffffu, (hu == um) ? (uint)hj : 0u);
        uint bal = __ballot_sync(0xffffffffu, hu == um && hj == jm);
        wlane = __ffs(bal) - 1;
        wd = iordu(um);
    }

    for (int tile = 0; tile < NN; tile += TILE) {
        if (tile) {
            __syncthreads();
            for (int j = tid; j < TILE; j += 256) {
                int g = tile + j;
                float xx = X[g], yy = X[NN+g], zz = X[2*NN+g];
                float r = __fadd_rn(__fadd_rn(__fmul_rn(xx,xx), __fmul_rn(yy,yy)), __fmul_rn(zz,zz));
                s4[j] = make_float4(xx, yy, zz, r);
            }
            __syncthreads();
        }
        for (int k = (tile == 0 ? 32 : 0); k < TILE; k += 32) {
            float4 c = s4[k + lane];
            float dot = __fadd_rn(__fadd_rn(__fmul_rn(qx,c.x), __fmul_rn(qy,c.y)), __fmul_rn(qz,c.z));
            float d = __fsub_rn(__fadd_rn(qq, c.w), __fmul_rn(2.0f, dot));
            uint m = __ballot_sync(0xffffffffu, d <= wd);
            while (m) {
                int src = __ffs(m) - 1; m &= m - 1;
                float cd = __shfl_sync(0xffffffffu, d, src);
                int cj = tile + k + src;
                uint cu = ordu(cd);
                if (cu < um || (cu == um && cj < jm)) {
                    if (lane == wlane) { hu = cu; hj = cj; }
                    um = __reduce_max_sync(0xffffffffu, hu);
                    jm = (int)__reduce_max_sync(0xffffffffu, (hu == um) ? (uint)hj : 0u);
                    uint bal = __ballot_sync(0xffffffffu, hu == um && hj == jm);
                    wlane = __ffs(bal) - 1;
                    wd = iordu(um);
                }
            }
        }
    }
    int outidx = 0;
    #pragma unroll
    for (int r = 0; r < KK; r++) {
        uint mu = __reduce_min_sync(0xffffffffu, hu);
        uint mj = __reduce_min_sync(0xffffffffu, (hu == mu) ? (uint)hj : (uint)IINF);
        if (lane == r) outidx = (int)mj;
        if (hu == mu && hj == (int)mj) { hu = 0xffffffffu; hj = IINF; }
    }
    if (lane < KK) g_knn[((size_t)b*NP + q)*KK + lane] = outidx;
}

// ---------------- gather new_xyz ----------------
__global__ void k_nx(const float* __restrict__ xyz, float* __restrict__ out) {
    int i = blockIdx.x*256 + threadIdx.x;
    int b = i >> 11, q = i & 2047, n = g_fps[i];
    #pragma unroll
    for (int c = 0; c < 3; c++)
        out[((size_t)b*3 + c)*NP + q] = xyz[((size_t)b*3 + c)*NN + n];
}

// ---------------- Z1 = W1[:,3:] @ points, per point ----------------
__global__ __launch_bounds__(128) void k_z1(const float* __restrict__ pts,
                                            const float* __restrict__ W1) {
    __shared__ float w[FF*FF];
    int tid = threadIdx.x;
    for (int i = tid; i < FF*FF; i += 128) w[i] = W1[(i>>6)*67 + 3 + (i&63)];
    __syncthreads();
    int p = blockIdx.x*128 + tid;
    int b = p >> 13, n = p & (NN-1);
    float xv[FF];
    #pragma unroll
    for (int f = 0; f < FF; f++) xv[f] = pts[((size_t)b*FF + f)*NN + n];
    float* zr = g_Z1 + (size_t)p*FF;
    for (int o = 0; o < FF; o += 4) {
        float a0=0.f, a1=0.f, a2=0.f, a3=0.f;
        #pragma unroll
        for (int f = 0; f < FF; f++) {
            float xf = xv[f];
            a0 = fmaf(w[(o+0)*FF+f], xf, a0);
            a1 = fmaf(w[(o+1)*FF+f], xf, a1);
            a2 = fmaf(w[(o+2)*FF+f], xf, a2);
            a3 = fmaf(w[(o+3)*FF+f], xf, a3);
        }
        *(float4*)(zr + o) = make_float4(a0, a1, a2, a3);
    }
}

// ---------------- pass1: y1 -> g_buf channel-major ----------------
__global__ __launch_bounds__(128) void k_p1(const float* __restrict__ xyz,
                                            const float* __restrict__ W1,
                                            const float* __restrict__ b1,
                                            const float* __restrict__ nxyz) {
    __shared__ float w0[64], w1s[64], w2s[64], bb[64];
    int tid = threadIdx.x;
    if (tid < 64) {
        w0[tid]  = W1[tid*67 + 0]; w1s[tid] = W1[tid*67 + 1];
        w2s[tid] = W1[tid*67 + 2]; bb[tid]  = b1[tid];
    }
    __syncthreads();
    int pos = blockIdx.x*128 + tid;
    int b = pos >> 15, q = (pos >> 4) & 2047, n = g_knn[pos];
    float cx = nxyz[((size_t)b*3+0)*NP+q], cy = nxyz[((size_t)b*3+1)*NP+q], cz = nxyz[((size_t)b*3+2)*NP+q];
    const float* X = xyz + (size_t)b*3*NN;
    float dx = X[n]-cx, dy = X[NN+n]-cy, dz = X[2*NN+n]-cz;
    const float4* zr = (const float4*)(g_Z1 + (size_t)(b*NN + n)*FF);
    #pragma unroll
    for (int i = 0; i < 16; i++) {
        float4 v = zr[i]; int o = 4*i;
        g_buf[(size_t)(o+0)*PP+pos] = fmaf(w2s[o+0],dz, fmaf(w1s[o+0],dy, fmaf(w0[o+0],dx, v.x+bb[o+0])));
        g_buf[(size_t)(o+1)*PP+pos] = fmaf(w2s[o+1],dz, fmaf(w1s[o+1],dy, fmaf(w0[o+1],dx, v.y+bb[o+1])));
        g_buf[(size_t)(o+2)*PP+pos] = fmaf(w2s[o+2],dz, fmaf(w1s[o+2],dy, fmaf(w0[o+2],dx, v.z+bb[o+2])));
        g_buf[(size_t)(o+3)*PP+pos] = fmaf(w2s[o+3],dz, fmaf(w1s[o+3],dy, fmaf(w0[o+3],dx, v.w+bb[o+3])));
    }
}

// ---------------- per-channel sum/sumsq ----------------
__global__ __launch_bounds__(256) void k_st(int which) {
    int o = blockIdx.y;
    const float* src = g_buf + (size_t)o*PP + blockIdx.x*(PP/16);
    float s = 0.f, s2 = 0.f;
    for (int i = threadIdx.x; i < PP/16; i += 256) {
        float v = src[i]; s += v; s2 = fmaf(v, v, s2);
    }
    #pragma unroll
    for (int off = 16; off; off >>= 1) {
        s  += __shfl_down_sync(0xffffffffu, s,  off);
        s2 += __shfl_down_sync(0xffffffffu, s2, off);
    }
    __shared__ float as[8], as2[8];
    int wid = threadIdx.x >> 5;
    if ((threadIdx.x & 31) == 0) { as[wid] = s; as2[wid] = s2; }
    __syncthreads();
    if (threadIdx.x == 0) {
        float ts = 0.f, ts2 = 0.f;
        #pragma unroll
        for (int w = 0; w < 8; w++) { ts += as[w]; ts2 += as2[w]; }
        atomicAdd(g_stats + which*128 + o, ts);
        atomicAdd(g_stats + which*128 + 64 + o, ts2);
    }
}

__global__ void k_fin(const float* __restrict__ gam, const float* __restrict__ bet, int which) {
    int o = threadIdx.x;
    float m = g_stats[which*128 + o] / (float)PP;
    float v = g_stats[which*128 + 64 + o] / (float)PP - m*m;
    v = fmaxf(v, 0.f);
    float sc = gam[o] * rsqrtf(v + 1e-5f);
    g_sc[which*128 + o] = sc;
    g_sc[which*128 + 64 + o] = bet[o] - m*sc;
}

// ---------------- pass2: bn1+relu -> conv2 (in place) ----------------
__global__ __launch_bounds__(128) void k_p2(const float* __restrict__ W2, const float* __restrict__ b2) {
    __shared__ float w[64*64];
    __shared__ float sc[64], sh[64], bb[64];
    int tid = threadIdx.x;
    for (int i = tid; i < 64*64; i += 128) w[i] = W2[i];
    if (tid < 64) { sc[tid] = g_sc[tid]; sh[tid] = g_sc[64+tid]; bb[tid] = b2[tid]; }
    __syncthreads();
    int pos = blockIdx.x*128 + tid;
    float h[64];
    #pragma unroll
    for (int o = 0; o < 64; o++) {
        float y = g_buf[(size_t)o*PP + pos];
        h[o] = fmaxf(fmaf(y, sc[o], sh[o]), 0.f);
    }
    for (int o = 0; o < 64; o++) {
        float a = bb[o];
        const float* wr = w + o*64;
        #pragma unroll
        for (int f = 0; f < 64; f++) a = fmaf(wr[f], h[f], a);
        g_buf[(size_t)o*PP + pos] = a;
    }
}

// ---------------- pass3: bn2+relu -> conv3 -> max over K ----------------
__global__ __launch_bounds__(128) void k_p3(const float* __restrict__ W3, const float* __restrict__ b3,
                                            float* __restrict__ outf) {
    __shared__ float w[128*64];
    __shared__ float sc[64], sh[64], bb[128];
    int tid = threadIdx.x;
    for (int i = tid; i < 128*64; i += 128) w[i] = W3[i];
    if (tid < 64) { sc[tid] = g_sc[128+tid]; sh[tid] = g_sc[192+tid]; }
    if (tid < 128) bb[tid] = b3[tid];
    __syncthreads();
    int pos = blockIdx.x*128 + tid;
    float h[64];
    #pragma unroll
    for (int o = 0; o < 64; o++) {
        float y = g_buf[(size_t)o*PP + pos];
        h[o] = fmaxf(fmaf(y, sc[o], sh[o]), 0.f);
    }
    int lane = tid & 15;
    int q = pos >> 4;
    int b = q >> 11, qq = q & 2047;
    for (int c = 0; c < 4; c++) {
        float acc[32];
        #pragma unroll
        for (int o = 0; o < 32; o++) {
            const float* wr = w + (c*32 + o)*64;
            float a = bb[c*32 + o];
            #pragma unroll
            for (int f = 0; f < 64; f++) a = fmaf(wr[f], h[f], a);
            acc[o] = a;
        }
        #pragma unroll
        for (int o = 0; o < 32; o++) {
            float v = acc[o];
            #pragma unroll
            for (int off = 1; off < 16; off <<= 1)
                v = fmaxf(v, __shfl_xor_sync(0xffffffffu, v, off));
            acc[o] = v;
        }
        #pragma unroll
        for (int o = 0; o < 32; o++)
            if ((o & 15) == lane)
                outf[((size_t)b*128 + c*32 + o)*NP + qq] = acc[o];
    }
}

extern "C" void kernel_launch(void* const* d_in, const int* in_sizes, int n_in,
                              void* d_out, int out_size) {
    const float* xyz = (const float*)d_in[0];
    const float* pts = (const float*)d_in[1];
    const float* W1  = (const float*)d_in[2];
    const float* b1  = (const float*)d_in[3];
    const float* g1  = (const float*)d_in[4];
    const float* be1 = (const float*)d_in[5];
    const float* W2  = (const float*)d_in[6];
    const float* b2  = (const float*)d_in[7];
    const float* g2  = (const float*)d_in[8];
    const float* be2 = (const float*)d_in[9];
    const float* W3  = (const float*)d_in[10];
    const float* b3  = (const float*)d_in[11];
    float* out  = (float*)d_out;
    float* onx  = out;                       // new_xyz (B,3,NP)
    float* ofe  = out + (size_t)BB*3*NP;     // new_feat (B,128,NP)

    static cudaStream_t sA = nullptr, sB = nullptr, sC = nullptr;
    static cudaEvent_t ev0 = nullptr, evA = nullptr, evB = nullptr, evC = nullptr;
    if (!sA) {
        cudaStreamCreateWithFlags(&sA, cudaStreamNonBlocking);
        cudaStreamCreateWithFlags(&sB, cudaStreamNonBlocking);
        cudaStreamCreateWithFlags(&sC, cudaStreamNonBlocking);
        cudaEventCreateWithFlags(&ev0, cudaEventDisableTiming);
        cudaEventCreateWithFlags(&evA, cudaEventDisableTiming);
        cudaEventCreateWithFlags(&evB, cudaEventDisableTiming);
        cudaEventCreateWithFlags(&evC, cudaEventDisableTiming);
    }

    const int FPS_SM = (3*NN + 32)*4;
    cudaFuncSetAttribute(k_fps, cudaFuncAttributeMaxDynamicSharedMemorySize, FPS_SM);

    // stream 0: zero stats + progress flags, then fork
    k_zero<<<1, 256>>>();
    cudaEventRecord(ev0, 0);

    // producer (submitted first -> resident first: only 8 blocks)
    cudaStreamWaitEvent(sA, ev0, 0);
    k_fps<<<BB, 256, FPS_SM, sA>>>(xyz);
    cudaEventRecord(evA, sA);

    // consumer: self-pacing KNN at full occupancy (16KB static smem)
    cudaStreamWaitEvent(sB, ev0, 0);
    k_knn<<<dim3(NP/8, BB), 256, 0, sB>>>(xyz);
    cudaEventRecord(evB, sB);

    // independent: Z1 precompute
    cudaStreamWaitEvent(sC, ev0, 0);
    k_z1<<<PTSN/128, 128, 0, sC>>>(pts, W1);
    cudaEventRecord(evC, sC);

    // join: k_nx needs g_fps
    cudaStreamWaitEvent(0, evA, 0);
    k_nx<<<(BB*NP)/256, 256>>>(xyz, onx);

    // join: p1 needs g_knn + g_Z1 (+ zeroed stats already on stream 0)
    cudaStreamWaitEvent(0, evB, 0);
    cudaStreamWaitEvent(0, evC, 0);
    k_p1<<<PP/128, 128>>>(xyz, W1, b1, onx);
    k_st<<<dim3(16, 64), 256>>>(0);
    k_fin<<<1, 64>>>(g1, be1, 0);
    k_p2<<<PP/128, 128>>>(W2, b2);
    k_st<<<dim3(16, 64), 256>>>(1);
    k_fin<<<1, 64>>>(g2, be2, 1);
    k_p3<<<PP/128, 128>>>(W3, b3, ofe);
}

// round 17
// speedup vs baseline: 1.2923x; 1.0136x over previous
#include <cuda_runtime.h>

#define BB 8
#define NN 8192
#define NP 2048
#define KK 16
#define FF 64
#define PP (BB*NP*KK)
#define PTSN (BB*NN)
#define IINF 0x7fffffff
#define TILE 1024

typedef unsigned long long ull;
typedef unsigned int uint;

__device__ float g_Z1[(size_t)PTSN*FF];
__device__ float g_buf[(size_t)PP*FF];
__device__ int   g_fps[BB*NP];
__device__ int   g_knn[PP];
__device__ float g_stats[256];
__device__ float g_sc[256];
__device__ int   g_prog[BB];

__global__ void k_zero() {
    g_stats[threadIdx.x] = 0.f;
    if (threadIdx.x < BB) g_prog[threadIdx.x] = 0;
}

// ---- packed f32x2 helpers (per-lane IEEE rn, identical to scalar) ----
__device__ __forceinline__ ull pk2(float lo, float hi) {
    ull r; asm("mov.b64 %0, {%1,%2};" : "=l"(r) : "f"(lo), "f"(hi)); return r;
}
__device__ __forceinline__ void upk2(ull v, float& lo, float& hi) {
    asm("mov.b64 {%0,%1}, %2;" : "=f"(lo), "=f"(hi) : "l"(v));
}
__device__ __forceinline__ ull add2(ull a, ull b) {
    ull r; asm("add.rn.f32x2 %0, %1, %2;" : "=l"(r) : "l"(a), "l"(b)); return r;
}
__device__ __forceinline__ ull mul2(ull a, ull b) {
    ull r; asm("mul.rn.f32x2 %0, %1, %2;" : "=l"(r) : "l"(a), "l"(b)); return r;
}

__device__ __forceinline__ uint ordu(float d) {
    uint u = __float_as_uint(d);
    return u ^ (((uint)((int)u >> 31)) | 0x80000000u);
}
__device__ __forceinline__ float iordu(uint u) {
    uint v = (u & 0x80000000u) ? (u ^ 0x80000000u) : ~u;
    return __uint_as_float(v);
}

// ---------------- FPS producer: one block/batch, publishes progress ----------------
__global__ __launch_bounds__(256) void k_fps(const float* __restrict__ xyz) {
    extern __shared__ float sm[];
    float* sx = sm; float* sy = sm + NN; float* sz = sm + 2*NN;
    uint* rvu = (uint*)(sm + 3*NN);     // 16 (double-buffered 2x8)
    int*  ri  = (int*)(rvu + 16);       // 16

    int b = blockIdx.x, tid = threadIdx.x, lane = tid & 31, wid = tid >> 5;
    int base = tid*32;
    const float* X = xyz + (size_t)b*3*NN;

    ull xp[16], yp[16], zp[16];
    float dmin[32];
    #pragma unroll
    for (int i = 0; i < 32; i += 4) {
        float4 vx = *(const float4*)(X + base + i);
        float4 vy = *(const float4*)(X + NN + base + i);
        float4 vz = *(const float4*)(X + 2*NN + base + i);
        xp[i/2]   = pk2(vx.x, vx.y); xp[i/2+1] = pk2(vx.z, vx.w);
        yp[i/2]   = pk2(vy.x, vy.y); yp[i/2+1] = pk2(vy.z, vy.w);
        zp[i/2]   = pk2(vz.x, vz.y); zp[i/2+1] = pk2(vz.z, vz.w);
        sx[base+i]=vx.x; sx[base+i+1]=vx.y; sx[base+i+2]=vx.z; sx[base+i+3]=vx.w;
        sy[base+i]=vy.x; sy[base+i+1]=vy.y; sy[base+i+2]=vy.z; sy[base+i+3]=vy.w;
        sz[base+i]=vz.x; sz[base+i+1]=vz.y; sz[base+i+2]=vz.z; sz[base+i+3]=vz.w;
    }
    #pragma unroll
    for (int i = 0; i < 32; i++) dmin[i] = 1e10f;

    float px = X[0], py = X[NN], pz = X[2*NN];
    if (tid == 0) g_fps[b*NP] = 0;
    __syncthreads();

    for (int t = 1; t < NP; t++) {
        ull npx = pk2(-px, -px), npy = pk2(-py, -py), npz = pk2(-pz, -pz);
        float bestv = 0.f; int besti = IINF;
        #pragma unroll
        for (int j = 0; j < 16; j++) {
            ull dx = add2(xp[j], npx);
            ull dy = add2(yp[j], npy);
            ull dz = add2(zp[j], npz);
            ull d2 = add2(add2(mul2(dx,dx), mul2(dy,dy)), mul2(dz,dz));
            float d0, d1; upk2(d2, d0, d1);
            int i0 = 2*j, i1 = 2*j + 1;
            dmin[i0] = fminf(dmin[i0], d0);
            if (dmin[i0] > bestv) { bestv = dmin[i0]; besti = base + i0; }
            dmin[i1] = fminf(dmin[i1], d1);
            if (dmin[i1] > bestv) { bestv = dmin[i1]; besti = base + i1; }
        }
        uint u  = __float_as_uint(bestv);
        uint um = __reduce_max_sync(0xffffffffu, u);
        uint wini = __reduce_min_sync(0xffffffffu, (u == um) ? (uint)besti : (uint)IINF);
        int bufo = (t & 1)*8;
        if (lane == 0) { rvu[bufo + wid] = um; ri[bufo + wid] = (int)wini; }
        __syncthreads();
        uint u2 = (lane < 8) ? rvu[bufo + lane] : 0u;
        int  j2 = (lane < 8) ? ri[bufo + lane]  : IINF;
        uint um2 = __reduce_max_sync(0xffffffffu, u2);
        uint jw  = __reduce_min_sync(0xffffffffu, (u2 == um2) ? (uint)j2 : (uint)IINF);
        int win = (int)jw;
        px = sx[win]; py = sy[win]; pz = sz[win];
        if (tid == 0) {
            g_fps[b*NP + t] = win;
            if ((t & 7) == 0 || t == NP-1) {
                __threadfence();
                *(volatile int*)&g_prog[b] = t;
            }
        }
    }
}

// ---------------- KNN consumer + fused pass1 ----------------
__global__ __launch_bounds__(256) void k_knnp1(const float* __restrict__ xyz,
                                               const float* __restrict__ W1,
                                               const float* __restrict__ b1) {
    __shared__ float4 s4[TILE];
    __shared__ float w0s[64], w1ss[64], w2ss[64], bbs[64];
    int tid = threadIdx.x, lane = tid & 31, wid = tid >> 5;
    int x = blockIdx.x, b = blockIdx.y;
    const float* X = xyz + (size_t)b*3*NN;

    // load tile 0 + weights while (possibly) waiting on the producer
    for (int j = tid; j < TILE; j += 256) {
        float xx = X[j], yy = X[NN+j], zz = X[2*NN+j];
        float r = __fadd_rn(__fadd_rn(__fmul_rn(xx,xx), __fmul_rn(yy,yy)), __fmul_rn(zz,zz));
        s4[j] = make_float4(xx, yy, zz, r);
    }
    if (tid < 64) {
        w0s[tid]  = W1[tid*67 + 0]; w1ss[tid] = W1[tid*67 + 1];
        w2ss[tid] = W1[tid*67 + 2]; bbs[tid]  = b1[tid];
    }
    if (tid == 0) {
        int qmax = x*8 + 7;
        while (*(volatile int*)&g_prog[b] < qmax) __nanosleep(128);
        __threadfence();
    }
    __syncthreads();

    int q = x*8 + wid;
    int qi = g_fps[b*NP + q];
    float qx = X[qi], qy = X[NN+qi], qz = X[2*NN+qi];
    float qq = __fadd_rn(__fadd_rn(__fmul_rn(qx,qx), __fmul_rn(qy,qy)), __fmul_rn(qz,qz));

    uint hu; int hj;
    uint um; int jm;
    int wlane; float wd;
    {
        float4 c = s4[lane];
        float dot = __fadd_rn(__fadd_rn(__fmul_rn(qx,c.x), __fmul_rn(qy,c.y)), __fmul_rn(qz,c.z));
        float d = __fsub_rn(__fadd_rn(qq, c.w), __fmul_rn(2.0f, dot));
        hu = ordu(d); hj = lane;
        um = __reduce_max_sync(0xffffffffu, hu);
        jm = (int)__reduce_max_sync(0xffffffffu, (hu == um) ? (uint)hj : 0u);
        uint bal = __ballot_sync(0xffffffffu, hu == um && hj == jm);
        wlane = __ffs(bal) - 1;
        wd = iordu(um);
    }

    for (int tile = 0; tile < NN; tile += TILE) {
        if (tile) {
            __syncthreads();
            for (int j = tid; j < TILE; j += 256) {
                int g = tile + j;
                float xx = X[g], yy = X[NN+g], zz = X[2*NN+g];
                float r = __fadd_rn(__fadd_rn(__fmul_rn(xx,xx), __fmul_rn(yy,yy)), __fmul_rn(zz,zz));
                s4[j] = make_float4(xx, yy, zz, r);
            }
            __syncthreads();
        }
        for (int k = (tile == 0 ? 32 : 0); k < TILE; k += 32) {
            float4 c = s4[k + lane];
            float dot = __fadd_rn(__fadd_rn(__fmul_rn(qx,c.x), __fmul_rn(qy,c.y)), __fmul_rn(qz,c.z));
            float d = __fsub_rn(__fadd_rn(qq, c.w), __fmul_rn(2.0f, dot));
            uint m = __ballot_sync(0xffffffffu, d <= wd);
            while (m) {
                int src = __ffs(m) - 1; m &= m - 1;
                float cd = __shfl_sync(0xffffffffu, d, src);
                int cj = tile + k + src;
                uint cu = ordu(cd);
                if (cu < um || (cu == um && cj < jm)) {
                    if (lane == wlane) { hu = cu; hj = cj; }
                    um = __reduce_max_sync(0xffffffffu, hu);
                    jm = (int)__reduce_max_sync(0xffffffffu, (hu == um) ? (uint)hj : 0u);
                    uint bal = __ballot_sync(0xffffffffu, hu == um && hj == jm);
                    wlane = __ffs(bal) - 1;
                    wd = iordu(um);
                }
            }
        }
    }
    int outidx = 0;
    #pragma unroll
    for (int r = 0; r < KK; r++) {
        uint mu = __reduce_min_sync(0xffffffffu, hu);
        uint mj = __reduce_min_sync(0xffffffffu, (hu == mu) ? (uint)hj : (uint)IINF);
        if (lane == r) outidx = (int)mj;
        if (hu == mu && hj == (int)mj) { hu = 0xffffffffu; hj = IINF; }
    }
    if (lane < KK) g_knn[((size_t)b*NP + q)*KK + lane] = outidx;

    // ---- fused pass1: this block's 128 positions (8 queries x 16 neighbors) ----
    __syncthreads();   // g_knn writes visible block-wide; weights loaded
    if (tid < 128) {
        int q2 = x*8 + (tid >> 4);
        int kk = tid & 15;
        int pos = ((b << 11) + q2)*16 + kk;             // == global position index
        int n = g_knn[(size_t)(b*NP + q2)*KK + kk];
        int qi2 = g_fps[b*NP + q2];
        float cx = X[qi2], cy = X[NN+qi2], cz = X[2*NN+qi2];
        float dx = X[n]-cx, dy = X[NN+n]-cy, dz = X[2*NN+n]-cz;
        const float4* zr = (const float4*)(g_Z1 + (size_t)(b*NN + n)*FF);
        #pragma unroll
        for (int i = 0; i < 16; i++) {
            float4 v = zr[i]; int o = 4*i;
            g_buf[(size_t)(o+0)*PP+pos] = fmaf(w2ss[o+0],dz, fmaf(w1ss[o+0],dy, fmaf(w0s[o+0],dx, v.x+bbs[o+0])));
            g_buf[(size_t)(o+1)*PP+pos] = fmaf(w2ss[o+1],dz, fmaf(w1ss[o+1],dy, fmaf(w0s[o+1],dx, v.y+bbs[o+1])));
            g_buf[(size_t)(o+2)*PP+pos] = fmaf(w2ss[o+2],dz, fmaf(w1ss[o+2],dy, fmaf(w0s[o+2],dx, v.z+bbs[o+2])));
            g_buf[(size_t)(o+3)*PP+pos] = fmaf(w2ss[o+3],dz, fmaf(w1ss[o+3],dy, fmaf(w0s[o+3],dx, v.w+bbs[o+3])));
        }
    }
}

// ---------------- gather new_xyz ----------------
__global__ void k_nx(const float* __restrict__ xyz, float* __restrict__ out) {
    int i = blockIdx.x*256 + threadIdx.x;
    int b = i >> 11, q = i & 2047, n = g_fps[i];
    #pragma unroll
    for (int c = 0; c < 3; c++)
        out[((size_t)b*3 + c)*NP + q] = xyz[((size_t)b*3 + c)*NN + n];
}

// ---------------- Z1 = W1[:,3:] @ points, per point ----------------
__global__ __launch_bounds__(128) void k_z1(const float* __restrict__ pts,
                                            const float* __restrict__ W1) {
    __shared__ float w[FF*FF];
    int tid = threadIdx.x;
    for (int i = tid; i < FF*FF; i += 128) w[i] = W1[(i>>6)*67 + 3 + (i&63)];
    __syncthreads();
    int p = blockIdx.x*128 + tid;
    int b = p >> 13, n = p & (NN-1);
    float xv[FF];
    #pragma unroll
    for (int f = 0; f < FF; f++) xv[f] = pts[((size_t)b*FF + f)*NN + n];
    float* zr = g_Z1 + (size_t)p*FF;
    for (int o = 0; o < FF; o += 4) {
        float a0=0.f, a1=0.f, a2=0.f, a3=0.f;
        #pragma unroll
        for (int f = 0; f < FF; f++) {
            float xf = xv[f];
            a0 = fmaf(w[(o+0)*FF+f], xf, a0);
            a1 = fmaf(w[(o+1)*FF+f], xf, a1);
            a2 = fmaf(w[(o+2)*FF+f], xf, a2);
            a3 = fmaf(w[(o+3)*FF+f], xf, a3);
        }
        *(float4*)(zr + o) = make_float4(a0, a1, a2, a3);
    }
}

// ---------------- per-channel sum/sumsq ----------------
__global__ __launch_bounds__(256) void k_st(int which) {
    int o = blockIdx.y;
    const float* src = g_buf + (size_t)o*PP + blockIdx.x*(PP/16);
    float s = 0.f, s2 = 0.f;
    for (int i = threadIdx.x; i < PP/16; i += 256) {
        float v = src[i]; s += v; s2 = fmaf(v, v, s2);
    }
    #pragma unroll
    for (int off = 16; off; off >>= 1) {
        s  += __shfl_down_sync(0xffffffffu, s,  off);
        s2 += __shfl_down_sync(0xffffffffu, s2, off);
    }
    __shared__ float as[8], as2[8];
    int wid = threadIdx.x >> 5;
    if ((threadIdx.x & 31) == 0) { as[wid] = s; as2[wid] = s2; }
    __syncthreads();
    if (threadIdx.x == 0) {
        float ts = 0.f, ts2 = 0.f;
        #pragma unroll
        for (int w = 0; w < 8; w++) { ts += as[w]; ts2 += as2[w]; }
        atomicAdd(g_stats + which*128 + o, ts);
        atomicAdd(g_stats + which*128 + 64 + o, ts2);
    }
}

__global__ void k_fin(const float* __restrict__ gam, const float* __restrict__ bet, int which) {
    int o = threadIdx.x;
    float m = g_stats[which*128 + o] / (float)PP;
    float v = g_stats[which*128 + 64 + o] / (float)PP - m*m;
    v = fmaxf(v, 0.f);
    float sc = gam[o] * rsqrtf(v + 1e-5f);
    g_sc[which*128 + o] = sc;
    g_sc[which*128 + 64 + o] = bet[o] - m*sc;
}

// ---------------- pass2: bn1+relu -> conv2 (in place) ----------------
__global__ __launch_bounds__(128) void k_p2(const float* __restrict__ W2, const float* __restrict__ b2) {
    __shared__ float w[64*64];
    __shared__ float sc[64], sh[64], bb[64];
    int tid = threadIdx.x;
    for (int i = tid; i < 64*64; i += 128) w[i] = W2[i];
    if (tid < 64) { sc[tid] = g_sc[tid]; sh[tid] = g_sc[64+tid]; bb[tid] = b2[tid]; }
    __syncthreads();
    int pos = blockIdx.x*128 + tid;
    float h[64];
    #pragma unroll
    for (int o = 0; o < 64; o++) {
        float y = g_buf[(size_t)o*PP + pos];
        h[o] = fmaxf(fmaf(y, sc[o], sh[o]), 0.f);
    }
    for (int o = 0; o < 64; o++) {
        float a = bb[o];
        const float* wr = w + o*64;
        #pragma unroll
        for (int f = 0; f < 64; f++) a = fmaf(wr[f], h[f], a);
        g_buf[(size_t)o*PP + pos] = a;
    }
}

// ---------------- pass3: bn2+relu -> conv3 -> max over K ----------------
__global__ __launch_bounds__(128) void k_p3(const float* __restrict__ W3, const float* __restrict__ b3,
                                            float* __restrict__ outf) {
    __shared__ float w[128*64];
    __shared__ float sc[64], sh[64], bb[128];
    int tid = threadIdx.x;
    for (int i = tid; i < 128*64; i += 128) w[i] = W3[i];
    if (tid < 64) { sc[tid] = g_sc[128+tid]; sh[tid] = g_sc[192+tid]; }
    if (tid < 128) bb[tid] = b3[tid];
    __syncthreads();
    int pos = blockIdx.x*128 + tid;
    float h[64];
    #pragma unroll
    for (int o = 0; o < 64; o++) {
        float y = g_buf[(size_t)o*PP + pos];
        h[o] = fmaxf(fmaf(y, sc[o], sh[o]), 0.f);
    }
    int lane = tid & 15;
    int q = pos >> 4;
    int b = q >> 11, qq = q & 2047;
    for (int c = 0; c < 4; c++) {
        float acc[32];
        #pragma unroll
        for (int o = 0; o < 32; o++) {
            const float* wr = w + (c*32 + o)*64;
            float a = bb[c*32 + o];
            #pragma unroll
            for (int f = 0; f < 64; f++) a = fmaf(wr[f], h[f], a);
            acc[o] = a;
        }
        #pragma unroll
        for (int o = 0; o < 32; o++) {
            float v = acc[o];
            #pragma unroll
            for (int off = 1; off < 16; off <<= 1)
                v = fmaxf(v, __shfl_xor_sync(0xffffffffu, v, off));
            acc[o] = v;
        }
        #pragma unroll
        for (int o = 0; o < 32; o++)
            if ((o & 15) == lane)
                outf[((size_t)b*128 + c*32 + o)*NP + qq] = acc[o];
    }
}

extern "C" void kernel_launch(void* const* d_in, const int* in_sizes, int n_in,
                              void* d_out, int out_size) {
    const float* xyz = (const float*)d_in[0];
    const float* pts = (const float*)d_in[1];
    const float* W1  = (const float*)d_in[2];
    const float* b1  = (const float*)d_in[3];
    const float* g1  = (const float*)d_in[4];
    const float* be1 = (const float*)d_in[5];
    const float* W2  = (const float*)d_in[6];
    const float* b2  = (const float*)d_in[7];
    const float* g2  = (const float*)d_in[8];
    const float* be2 = (const float*)d_in[9];
    const float* W3  = (const float*)d_in[10];
    const float* b3  = (const float*)d_in[11];
    float* out  = (float*)d_out;
    float* onx  = out;                       // new_xyz (B,3,NP)
    float* ofe  = out + (size_t)BB*3*NP;     // new_feat (B,128,NP)

    static cudaStream_t sA = nullptr, sB = nullptr, sC = nullptr;
    static cudaEvent_t ev0 = nullptr, evA = nullptr, evB = nullptr, evC = nullptr;
    if (!sA) {
        cudaStreamCreateWithFlags(&sA, cudaStreamNonBlocking);
        cudaStreamCreateWithFlags(&sB, cudaStreamNonBlocking);
        cudaStreamCreateWithFlags(&sC, cudaStreamNonBlocking);
        cudaEventCreateWithFlags(&ev0, cudaEventDisableTiming);
        cudaEventCreateWithFlags(&evA, cudaEventDisableTiming);
        cudaEventCreateWithFlags(&evB, cudaEventDisableTiming);
        cudaEventCreateWithFlags(&evC, cudaEventDisableTiming);
    }

    const int FPS_SM = (3*NN + 32)*4;
    cudaFuncSetAttribute(k_fps, cudaFuncAttributeMaxDynamicSharedMemorySize, FPS_SM);

    // stream 0: zero stats + progress flags, then fork
    k_zero<<<1, 256>>>();
    cudaEventRecord(ev0, 0);

    // producer (submitted first -> resident first: only 8 blocks)
    cudaStreamWaitEvent(sA, ev0, 0);
    k_fps<<<BB, 256, FPS_SM, sA>>>(xyz);
    cudaEventRecord(evA, sA);

    // Z1 precompute (must complete before fused knn+p1 reads g_Z1)
    cudaStreamWaitEvent(sC, ev0, 0);
    k_z1<<<PTSN/128, 128, 0, sC>>>(pts, W1);
    cudaEventRecord(evC, sC);

    // consumer: self-pacing KNN + fused pass1 (waits on z1 to avoid any race/spin)
    cudaStreamWaitEvent(sB, ev0, 0);
    cudaStreamWaitEvent(sB, evC, 0);
    k_knnp1<<<dim3(NP/8, BB), 256, 0, sB>>>(xyz, W1, b1);
    cudaEventRecord(evB, sB);

    // join: k_nx needs g_fps
    cudaStreamWaitEvent(0, evA, 0);
    k_nx<<<(BB*NP)/256, 256>>>(xyz, onx);

    // join: stats need the fused kernel's g_buf writes
    cudaStreamWaitEvent(0, evB, 0);
    k_st<<<dim3(16, 64), 256>>>(0);
    k_fin<<<1, 64>>>(g1, be1, 0);
    k_p2<<<PP/128, 128>>>(W2, b2);
    k_st<<<dim3(16, 64), 256>>>(1);
    k_fin<<<1, 64>>>(g2, be2, 1);
    k_p3<<<PP/128, 128>>>(W3, b3, ofe);
}